// round 13
// baseline (speedup 1.0000x reference)
#include <cuda_runtime.h>
#include <cuda_fp16.h>
#include <math.h>
#include <stdint.h>

// ---------------- problem constants ----------------
#define BATCH   128
#define OBS_H   2
#define NTOK    291
#define M_TOK   (BATCH*NTOK)   // 37248 = 291*128
#define D_EMB   384
#define NHEAD   6
#define NLAYER  12
#define N_IMG   144
#define PK      192
#define M_PATCH (BATCH*OBS_H*N_IMG)

// ---------------- scratch ----------------
__device__ float g_x  [M_TOK * D_EMB];
__device__ float g_att[M_PATCH * D_EMB];
__device__ float g_st [BATCH * OBS_H * D_EMB];
__device__ float2 g_sA[3 * M_TOK];             // row-stat partials (x)
__device__ float2 g_sB[3 * M_TOK];             // row-stat partials (after proj)
__device__ __half g_xh[M_TOK*384];
__device__ __half g_ah[M_TOK*384];
__device__ __half g_bh[M_TOK*1536];
__device__ __half g_ph[M_PATCH*192];
__device__ __half g_q [BATCH*NHEAD*NTOK*64];
__device__ __half g_k [BATCH*NHEAD*NTOK*64];
__device__ __half g_v [BATCH*NHEAD*NTOK*64];
// transposed weights [N,K] fp16 (qkv/fc1 have ln-g folded in)
__device__ __half g_wq[12*1152*384];
__device__ __half g_wp[12*384*384];
__device__ __half g_w1[12*1536*384];
__device__ __half g_w2[12*384*1536];
__device__ __half g_wi[384*192];
// LN-fusion vectors: u = g@W, c = b@W + bias
__device__ float g_uq[12*1152], g_cq[12*1152];
__device__ float g_u1[12*1536], g_c1[12*1536];

__device__ __forceinline__ float gelu_tanh(float v) {
    const float c = 0.7978845608028654f;
    float u = c * (v + 0.044715f * v * v * v);
    return 0.5f * v * (1.0f + tanhf(u));
}

__device__ __forceinline__ uint32_t smem_u32(const void* p) {
    uint32_t a;
    asm("{ .reg .u64 t; cvta.to.shared.u64 t, %1; cvt.u32.u64 %0, t; }" : "=r"(a) : "l"(p));
    return a;
}

__device__ __forceinline__ void mma16816(float c[4], const uint32_t a[4], const uint32_t b[2]) {
    asm volatile(
        "mma.sync.aligned.m16n8k16.row.col.f32.f16.f16.f32 "
        "{%0,%1,%2,%3}, {%4,%5,%6,%7}, {%8,%9}, {%0,%1,%2,%3};\n"
        : "+f"(c[0]), "+f"(c[1]), "+f"(c[2]), "+f"(c[3])
        : "r"(a[0]), "r"(a[1]), "r"(a[2]), "r"(a[3]), "r"(b[0]), "r"(b[1]));
}
#define LDMX4(r0, r1, r2, r3, addr) \
    asm volatile("ldmatrix.sync.aligned.m8n8.x4.shared.b16 {%0,%1,%2,%3}, [%4];" \
        : "=r"(r0), "=r"(r1), "=r"(r2), "=r"(r3) : "r"(addr))
#define LDMX4T(r0, r1, r2, r3, addr) \
    asm volatile("ldmatrix.sync.aligned.m8n8.x4.trans.shared.b16 {%0,%1,%2,%3}, [%4];" \
        : "=r"(r0), "=r"(r1), "=r"(r2), "=r"(r3) : "r"(addr))

// =======================================================================
// fp16 HMMA GEMM. 128 threads = 4 warps (2x2), warp tile 64x64.
// BK=64, 3-stage cp.async pipeline, ONE sync per 64-k-tile.
// smem stage: A[128][72h] + B[128][72h], 144B rows (conflict-free), 36.9KB.
// EPI 0: +bias -> f32 C
// EPI 4: LN-fused -> scatter q/k/v fp16           (reads 3 stat partials)
// EPI 3: LN-fused + gelu -> fp16 Ch               (reads 3 stat partials)
// EPI 5: +bias+res -> f32 C, fp16 XH, stat partial (smem-reduced across warps)
// =======================================================================
#define ROWB      144
#define STAGE_B   (2*128*ROWB)        // 36864
#define GSMEM     (3*STAGE_B)         // 110592

template <int EPI>
__global__ void __launch_bounds__(128, 2) gemm_mma(
    const __half* __restrict__ A, const __half* __restrict__ B,
    const float* __restrict__ bias, const float* __restrict__ Rres,
    float* __restrict__ C, __half* __restrict__ Ch,
    __half* __restrict__ Qo, __half* __restrict__ Ko, __half* __restrict__ Vo,
    const float2* __restrict__ stats_in, float2* __restrict__ stats_out,
    const float* __restrict__ uvec, __half* __restrict__ XH,
    int N, int K)
{
    extern __shared__ __align__(16) char dyn[];
    const uint32_t sbase = smem_u32(dyn);
    const int tid = threadIdx.x, lane = tid & 31, warp = tid >> 5;
    const int wm = warp >> 1, wn = warp & 1;       // 2x2 warp grid
    const int bn = blockIdx.x, bm = blockIdx.y;

    float acc[4][8][4];
#pragma unroll
    for (int i = 0; i < 4; i++)
#pragma unroll
        for (int j = 0; j < 8; j++)
#pragma unroll
            for (int q = 0; q < 4; q++) acc[i][j][q] = 0.f;

    const char* gsrc[2] = {
        (const char*)(A + (size_t)bm * 128 * K),
        (const char*)(B + (size_t)bn * 128 * K) };
    const size_t rs = (size_t)K * 2;

// 64-k tile: per operand 128 rows x 128B (8 chunks of 16B) = 1024 chunks
#define LOADT(t_) do { \
    uint32_t db_ = sbase + ((t_) % 3) * STAGE_B; \
    size_t go_ = (size_t)(t_) * 128; \
    _Pragma("unroll") \
    for (int b_ = 0; b_ < 2; b_++) { \
        const char* g_ = gsrc[b_]; \
        uint32_t d_ = db_ + b_ * (128 * ROWB); \
        _Pragma("unroll") \
        for (int i_ = 0; i_ < 8; i_++) { \
            int idx_ = i_ * 128 + tid; \
            int r_ = idx_ >> 3, c_ = (idx_ & 7) * 16; \
            asm volatile("cp.async.cg.shared.global [%0], [%1], 16;" \
                :: "r"(d_ + r_ * ROWB + c_), "l"(g_ + (size_t)r_ * rs + go_ + c_) : "memory"); \
        } \
    } \
    asm volatile("cp.async.commit_group;" ::: "memory"); \
} while (0)

    const int T = K >> 6;
    LOADT(0);
    if (T > 1) LOADT(1);

    for (int t = 0; t < T; t++) {
        if (t + 1 < T) asm volatile("cp.async.wait_group 1;" ::: "memory");
        else           asm volatile("cp.async.wait_group 0;" ::: "memory");
        __syncthreads();
        // issue next-next tile loads FIRST so cp.async overlaps the mma burst
        if (t + 2 < T) LOADT(t + 2);
        const uint32_t sb = sbase + (t % 3) * STAGE_B;

#pragma unroll
        for (int ks = 0; ks < 4; ks++) {
            const int k0 = ks * 16;
            uint32_t bf[8][2];
#pragma unroll
            for (int pr = 0; pr < 4; pr++) {
                int trow = wn * 64 + pr * 16 + ((lane >> 4) & 1) * 8 + (lane & 7);
                int tcol = k0 + ((lane >> 3) & 1) * 8;
                uint32_t ab = sb + 128 * ROWB + trow * ROWB + tcol * 2;
                LDMX4(bf[2*pr][0], bf[2*pr][1], bf[2*pr+1][0], bf[2*pr+1][1], ab);
            }
#pragma unroll
            for (int i = 0; i < 4; i++) {
                int arow = wm * 64 + i * 16 + (lane & 7) + ((lane >> 3) & 1) * 8;
                int acol = k0 + ((lane >> 4) & 1) * 8;
                uint32_t aa = sb + arow * ROWB + acol * 2;
                uint32_t a4[4];
                LDMX4(a4[0], a4[1], a4[2], a4[3], aa);
#pragma unroll
                for (int j = 0; j < 8; j++) mma16816(acc[i][j], a4, bf[j]);
            }
        }
    }

    // EPI==5: per-row stat reduction buffer in (now-free) pipeline smem
    float2* sstat = (float2*)dyn;
    if (EPI == 5) {
        __syncthreads();                 // everyone done reading stage smem
        sstat[tid] = make_float2(0.f, 0.f);
        __syncthreads();
    }

    const float att_scale = 1.0f / sqrtf(64.0f + 1e-8f);

#pragma unroll
    for (int i = 0; i < 4; i++) {
        int row0 = bm * 128 + wm * 64 + i * 16 + (lane >> 2);
#pragma unroll
        for (int half_ = 0; half_ < 2; half_++) {
            int row = row0 + half_ * 8;
            float mu = 0.f, inv = 1.f;
            if (EPI == 3 || EPI == 4) {
                float2 p0 = stats_in[row];
                float2 p1 = stats_in[M_TOK + row];
                float2 p2 = stats_in[2 * M_TOK + row];
                float sx = p0.x + p1.x + p2.x;
                float sq = p0.y + p1.y + p2.y;
                mu = sx * (1.0f / 384.0f);
                inv = rsqrtf(sq * (1.0f / 384.0f) - mu * mu + 1e-5f);
            }
            float rsum = 0.f, rsq = 0.f;
#pragma unroll
            for (int j = 0; j < 8; j++) {
                int col = bn * 128 + wn * 64 + j * 8 + (lane & 3) * 2;
                float a0 = acc[i][j][half_ * 2 + 0];
                float a1 = acc[i][j][half_ * 2 + 1];
                if (EPI == 0) {
                    size_t off = (size_t)row * N + col;
                    *(float2*)(C + off) = make_float2(a0 + bias[col], a1 + bias[col + 1]);
                } else if (EPI == 4) {
                    float v0 = inv * (a0 - mu * uvec[col])     + bias[col];
                    float v1 = inv * (a1 - mu * uvec[col + 1]) + bias[col + 1];
                    int kind = col / 384;
                    int hh = (col % 384) >> 6;
                    int dd = col & 63;
                    int bb = row / NTOK, tt = row % NTOK;
                    size_t o3 = ((size_t)(bb * NHEAD + hh) * NTOK + tt) * 64 + dd;
                    if (kind == 0)
                        *(__half2*)(Qo + o3) = __floats2half2_rn(v0 * att_scale, v1 * att_scale);
                    else if (kind == 1)
                        *(__half2*)(Ko + o3) = __floats2half2_rn(v0, v1);
                    else
                        *(__half2*)(Vo + o3) = __floats2half2_rn(v0, v1);
                } else if (EPI == 3) {
                    float v0 = gelu_tanh(inv * (a0 - mu * uvec[col])     + bias[col]);
                    float v1 = gelu_tanh(inv * (a1 - mu * uvec[col + 1]) + bias[col + 1]);
                    size_t off = (size_t)row * N + col;
                    *(__half2*)((char*)Ch + off * 2) = __floats2half2_rn(v0, v1);
                } else { // EPI == 5
                    size_t off = (size_t)row * N + col;
                    float2 rr = *(const float2*)(Rres + off);
                    float v0 = a0 + bias[col]     + rr.x;
                    float v1 = a1 + bias[col + 1] + rr.y;
                    *(float2*)(C + off) = make_float2(v0, v1);
                    *(__half2*)((char*)XH + off * 2) = __floats2half2_rn(v0, v1);
                    rsum += v0 + v1;
                    rsq  += v0 * v0 + v1 * v1;
                }
            }
            if (EPI == 5) {
                // reduce over the 4 lanes covering this row, combine the 2
                // column-warps via smem atomics
                rsum += __shfl_xor_sync(~0u, rsum, 1); rsum += __shfl_xor_sync(~0u, rsum, 2);
                rsq  += __shfl_xor_sync(~0u, rsq, 1);  rsq  += __shfl_xor_sync(~0u, rsq, 2);
                if ((lane & 3) == 0) {
                    int rl = row - bm * 128;       // 0..127
                    atomicAdd(&sstat[rl].x, rsum);
                    atomicAdd(&sstat[rl].y, rsq);
                }
            }
        }
    }
    if (EPI == 5) {
        __syncthreads();
        stats_out[bn * M_TOK + bm * 128 + tid] = sstat[tid];
    }
}

// ---------------- weight transpose + fp16, optional g-fold ----
__global__ void wprep(const float* __restrict__ W, const float* __restrict__ g,
                      __half* __restrict__ Wh, int K, int N)
{
    __shared__ float t[32][33];
    const int l = blockIdx.z;
    const size_t lo = (size_t)l * K * N;
    const float* Wp = W + lo;
    const int kt = blockIdx.y * 32, nt = blockIdx.x * 32;
    const int tx = threadIdx.x, ty = threadIdx.y;
#pragma unroll
    for (int i = ty; i < 32; i += 8)
        t[i][tx] = Wp[(size_t)(kt + i) * N + nt + tx];
    __syncthreads();
    float gk = g ? g[l * K + kt + tx] : 1.0f;
#pragma unroll
    for (int i = ty; i < 32; i += 8)
        Wh[lo + (size_t)(nt + i) * K + kt + tx] = __float2half_rn(t[tx][i] * gk);
}

// ---------------- LN-fusion u/c prep ----
__global__ void prep_uc(const float* __restrict__ W, const float* __restrict__ g,
                        const float* __restrict__ b, const float* __restrict__ bias,
                        float* __restrict__ u, float* __restrict__ c, int N)
{
    const int l = blockIdx.y;
    const int n = blockIdx.x * 128 + threadIdx.x;
    const float* Wp = W + (size_t)l * 384 * N + n;
    const float* gp = g + l * 384;
    const float* bp = b + l * 384;
    float su = 0.f, sc = 0.f;
    for (int k = 0; k < 384; k++) {
        float w = Wp[(size_t)k * N];
        su = fmaf(gp[k], w, su);
        sc = fmaf(bp[k], w, sc);
    }
    u[l * N + n] = su;
    c[l * N + n] = sc + bias[l * N + n];
}

__global__ void lnf_kernel(const float* __restrict__ x, const float* __restrict__ w,
                           const float* __restrict__ b, float* __restrict__ out)
{
    size_t bi = blockIdx.x;
    const float* xr = x + (bi * NTOK + (NTOK - 1)) * D_EMB;
    int tid = threadIdx.x;
    float v0 = xr[tid], v1 = xr[tid + 128], v2 = xr[tid + 256];
    float s = v0 + v1 + v2, sq = v0*v0 + v1*v1 + v2*v2;
#pragma unroll
    for (int o = 16; o; o >>= 1) {
        s  += __shfl_xor_sync(~0u, s,  o);
        sq += __shfl_xor_sync(~0u, sq, o);
    }
    __shared__ float ws[4], wq[4], red[2];
    int warp = tid >> 5, lane = tid & 31;
    if (!lane) { ws[warp] = s; wq[warp] = sq; }
    __syncthreads();
    if (tid == 0) {
        float S = ws[0]+ws[1]+ws[2]+ws[3], Q = wq[0]+wq[1]+wq[2]+wq[3];
        float mean = S * (1.0f / 384.0f);
        red[0] = mean;
        red[1] = rsqrtf(Q * (1.0f / 384.0f) - mean * mean + 1e-5f);
    }
    __syncthreads();
    float mean = red[0], inv = red[1];
    out[bi * D_EMB + tid]       = (v0 - mean) * inv * w[tid]       + b[tid];
    out[bi * D_EMB + tid + 128] = (v1 - mean) * inv * w[tid + 128] + b[tid + 128];
    out[bi * D_EMB + tid + 256] = (v2 - mean) * inv * w[tid + 256] + b[tid + 256];
}

// ---------------- Flash attention on HMMA (fp32 softmax) ----------------
// No Q smem (gmem A-fragments). K and V both row-major [320][72h];
// V fragments fetched via ldmatrix.trans (no smem transpose pass).
#define KPAD 320
#define KSTR 72
#define ATT_SMEM_HALVES (2*KPAD*KSTR)
#define ATT_SMEM_BYTES  (ATT_SMEM_HALVES * 2)    // 92160

__global__ void __launch_bounds__(256, 2) attn_mma(
    const __half* __restrict__ Qb, const __half* __restrict__ Kb,
    const __half* __restrict__ Vb, __half* __restrict__ oh)
{
    extern __shared__ __half smh[];
    __half* Ks = smh;
    __half* Vs = smh + KPAD * KSTR;

    const int bh = blockIdx.x;
    const int b = bh / NHEAD, h = bh % NHEAD;
    const int tid = threadIdx.x, warp = tid >> 5, lane = tid & 31;
    const size_t ib = (size_t)bh * NTOK * 64;

    // fill K and V rows 0..290; zero V pad rows 291..319 (NaN*0 hazard in P@V)
    for (int idx = tid; idx < NTOK * 8; idx += 256) {
        int t = idx >> 3, s = idx & 7;
        ((int4*)(Ks + t * KSTR))[s] = ((const int4*)(Kb + ib + (size_t)t * 64))[s];
        ((int4*)(Vs + t * KSTR))[s] = ((const int4*)(Vb + ib + (size_t)t * 64))[s];
    }
    for (int idx = tid; idx < (KPAD - NTOK) * 8; idx += 256) {
        int t = NTOK + (idx >> 3), s = idx & 7;
        ((int4*)(Vs + t * KSTR))[s] = make_int4(0, 0, 0, 0);
    }
    __syncthreads();

    const uint32_t ks0 = smem_u32(Ks), vs0 = smem_u32(Vs);

    for (int tile = warp; tile < 19; tile += 8) {
        // ---- Q fragments straight from gmem (canonical m16n8k16 A layout) ----
        uint32_t qf[4][4];
        {
            int r0g = tile * 16 + (lane >> 2);
            int r1g = r0g + 8;
            if (r0g >= NTOK) r0g = NTOK - 1;
            if (r1g >= NTOK) r1g = NTOK - 1;
            const __half* Q0 = Qb + ib + (size_t)r0g * 64;
            const __half* Q1 = Qb + ib + (size_t)r1g * 64;
            int c0 = (lane & 3) * 2;
#pragma unroll
            for (int ks = 0; ks < 4; ks++) {
                qf[ks][0] = *(const uint32_t*)(Q0 + ks * 16 + c0);
                qf[ks][1] = *(const uint32_t*)(Q1 + ks * 16 + c0);
                qf[ks][2] = *(const uint32_t*)(Q0 + ks * 16 + c0 + 8);
                qf[ks][3] = *(const uint32_t*)(Q1 + ks * 16 + c0 + 8);
            }
        }
        float O[8][4];
#pragma unroll
        for (int j = 0; j < 8; j++)
#pragma unroll
            for (int q = 0; q < 4; q++) O[j][q] = 0.f;
        float mr0 = -1e30f, mr1 = -1e30f, lr0 = 0.f, lr1 = 0.f;

        for (int ch = 0; ch < 5; ch++) {
            float S[8][4];
#pragma unroll
            for (int j = 0; j < 8; j++)
#pragma unroll
                for (int q = 0; q < 4; q++) S[j][q] = 0.f;

#pragma unroll
            for (int ks = 0; ks < 4; ks++) {
#pragma unroll
                for (int kg = 0; kg < 4; kg++) {
                    int trow = ch * 64 + kg * 16 + ((lane >> 4) & 1) * 8 + (lane & 7);
                    int tcol = ks * 16 + ((lane >> 3) & 1) * 8;
                    uint32_t ad = ks0 + (trow * KSTR + tcol) * 2;
                    uint32_t bfr[4];
                    LDMX4(bfr[0], bfr[1], bfr[2], bfr[3], ad);
                    mma16816(S[kg * 2],     qf[ks], bfr);
                    mma16816(S[kg * 2 + 1], qf[ks], bfr + 2);
                }
            }

            float cm0 = -1e30f, cm1 = -1e30f;
#pragma unroll
            for (int j = 0; j < 8; j++) {
                int k0c = ch * 64 + j * 8 + (lane & 3) * 2;
                if (k0c >= NTOK)     { S[j][0] = -1e30f; S[j][2] = -1e30f; }
                if (k0c + 1 >= NTOK) { S[j][1] = -1e30f; S[j][3] = -1e30f; }
                cm0 = fmaxf(cm0, fmaxf(S[j][0], S[j][1]));
                cm1 = fmaxf(cm1, fmaxf(S[j][2], S[j][3]));
            }
            cm0 = fmaxf(cm0, __shfl_xor_sync(~0u, cm0, 1));
            cm0 = fmaxf(cm0, __shfl_xor_sync(~0u, cm0, 2));
            cm1 = fmaxf(cm1, __shfl_xor_sync(~0u, cm1, 1));
            cm1 = fmaxf(cm1, __shfl_xor_sync(~0u, cm1, 2));

            float mn0 = fmaxf(mr0, cm0), mn1 = fmaxf(mr1, cm1);
            float sc0 = __expf(mr0 - mn0), sc1 = __expf(mr1 - mn1);

            float cs0 = 0.f, cs1 = 0.f;
            uint32_t pf[4][4];
#pragma unroll
            for (int j = 0; j < 8; j++) {
                float e0 = __expf(S[j][0] - mn0), e1 = __expf(S[j][1] - mn0);
                float e2 = __expf(S[j][2] - mn1), e3 = __expf(S[j][3] - mn1);
                cs0 += e0 + e1; cs1 += e2 + e3;
                __half2 p01 = __floats2half2_rn(e0, e1);
                __half2 p23 = __floats2half2_rn(e2, e3);
                int jg = j >> 1, sl = (j & 1) * 2;
                pf[jg][sl]     = reinterpret_cast<uint32_t&>(p01);
                pf[jg][sl + 1] = reinterpret_cast<uint32_t&>(p23);
            }
            cs0 += __shfl_xor_sync(~0u, cs0, 1); cs0 += __shfl_xor_sync(~0u, cs0, 2);
            cs1 += __shfl_xor_sync(~0u, cs1, 1); cs1 += __shfl_xor_sync(~0u, cs1, 2);
            lr0 = lr0 * sc0 + cs0; lr1 = lr1 * sc1 + cs1;
            mr0 = mn0; mr1 = mn1;
#pragma unroll
            for (int j = 0; j < 8; j++) {
                O[j][0] *= sc0; O[j][1] *= sc0; O[j][2] *= sc1; O[j][3] *= sc1;
            }

            // ---- O += P @ V : V row-major, B-fragments via ldmatrix.trans ----
#pragma unroll
            for (int jg = 0; jg < 4; jg++) {
#pragma unroll
                for (int dg = 0; dg < 4; dg++) {
                    int trow = ch * 64 + jg * 16 + ((lane >> 3) & 1) * 8 + (lane & 7);
                    int tcol = dg * 16 + ((lane >> 4) & 1) * 8;
                    uint32_t ad = vs0 + (trow * KSTR + tcol) * 2;
                    uint32_t bfr[4];
                    LDMX4T(bfr[0], bfr[1], bfr[2], bfr[3], ad);
                    mma16816(O[dg * 2],     pf[jg], bfr);
                    mma16816(O[dg * 2 + 1], pf[jg], bfr + 2);
                }
            }
        }

        float inv0 = 1.0f / lr0, inv1 = 1.0f / lr1;
        int r0 = tile * 16 + (lane >> 2), r1 = r0 + 8;
#pragma unroll
        for (int j = 0; j < 8; j++) {
            int d = j * 8 + (lane & 3) * 2;
            if (r0 < NTOK) {
                __half2 hv = (r0 == NTOK - 1)
                    ? *(const __half2*)(Vb + ib + (size_t)(NTOK - 1) * 64 + d)
                    : __floats2half2_rn(O[j][0] * inv0, O[j][1] * inv0);
                *(__half2*)(oh + ((size_t)b * NTOK + r0) * D_EMB + h * 64 + d) = hv;
            }
            if (r1 < NTOK) {
                __half2 hv = (r1 == NTOK - 1)
                    ? *(const __half2*)(Vb + ib + (size_t)(NTOK - 1) * 64 + d)
                    : __floats2half2_rn(O[j][2] * inv1, O[j][3] * inv1);
                *(__half2*)(oh + ((size_t)b * NTOK + r1) * D_EMB + h * 64 + d) = hv;
            }
        }
    }
}

// ---------------- tokenizers ----------------
__global__ void st_kernel(const float* __restrict__ as, const float* __restrict__ w1,
                          const float* __restrict__ b1, const float* __restrict__ w2,
                          const float* __restrict__ b2, float* __restrict__ st)
{
    __shared__ float h1[32];
    int bt = blockIdx.x;
    int tid = threadIdx.x;
    float s0 = as[bt * 2], s1 = as[bt * 2 + 1];
    if (tid < 32) {
        float v = b1[tid] + s0 * w1[tid] + s1 * w1[32 + tid];
        h1[tid] = v > 0.f ? v : 0.f;
    }
    __syncthreads();
    float acc = b2[tid];
#pragma unroll
    for (int k = 0; k < 32; k++) acc = fmaf(h1[k], w2[k * 384 + tid], acc);
    st[(size_t)bt * 384 + tid] = acc;
}

__global__ void im2col_kernel(const float* __restrict__ img, __half* __restrict__ ph)
{
    int idx = blockIdx.x * 256 + threadIdx.x;
    int f = idx % 192;
    int rem = idx / 192;
    int pidx = rem % 144;
    int bt = rem / 144;
    int pr = f / 24, pc = (f % 24) / 3, c = f % 3;
    int hp = pidx / 12, wp = pidx % 12;
    ph[idx] = __float2half_rn(img[(((size_t)bt * 3 + c) * 96 + hp * 8 + pr) * 96 + wp * 8 + pc]);
}

// assemble residual stream + xh + stat partials (block per row, 128 thr)
__global__ void assemble_ln(const float* __restrict__ imgtok, const float* __restrict__ st,
                            const float* __restrict__ readout, const float* __restrict__ pos,
                            const float* __restrict__ img_temb, const float* __restrict__ st_temb,
                            float* __restrict__ x, __half* __restrict__ xh,
                            float2* __restrict__ stats)
{
    size_t row = blockIdx.x;
    int tok = (int)(row % NTOK);
    int b = (int)(row / NTOK);
    int tid = threadIdx.x;
    float v[3];
#pragma unroll
    for (int q = 0; q < 3; q++) {
        int d = tid + q * 128;
        float vv;
        if (tok == NTOK - 1) {
            vv = readout[d];
        } else {
            int t = tok / 145, r = tok % 145;
            if (r == 0) vv = st[((size_t)(b * 2 + t)) * 384 + d] + st_temb[t * 384 + d];
            else        vv = imgtok[((size_t)(b * 2 + t) * 144 + (r - 1)) * 384 + d] + img_temb[t * 384 + d];
        }
        vv += pos[tok * 384 + d];
        v[q] = vv;
        x[row * D_EMB + d] = vv;
        xh[row * D_EMB + d] = __float2half_rn(vv);
    }
    float s = v[0] + v[1] + v[2], sq = v[0]*v[0] + v[1]*v[1] + v[2]*v[2];
#pragma unroll
    for (int o = 16; o; o >>= 1) {
        s  += __shfl_xor_sync(~0u, s,  o);
        sq += __shfl_xor_sync(~0u, sq, o);
    }
    __shared__ float ws[4], wq[4];
    int warp = tid >> 5, lane = tid & 31;
    if (!lane) { ws[warp] = s; wq[warp] = sq; }
    __syncthreads();
    if (tid == 0) {
        stats[row] = make_float2(ws[0]+ws[1]+ws[2]+ws[3], wq[0]+wq[1]+wq[2]+wq[3]);
        stats[M_TOK + row] = make_float2(0.f, 0.f);
        stats[2 * M_TOK + row] = make_float2(0.f, 0.f);
    }
}

// ---------------- launch ----------------
extern "C" void kernel_launch(void* const* d_in, const int* in_sizes, int n_in,
                              void* d_out, int out_size)
{
    const float* images      = (const float*)d_in[0];
    const float* agent_state = (const float*)d_in[1];
    const float* img_proj_w  = (const float*)d_in[2];
    const float* img_proj_b  = (const float*)d_in[3];
    const float* img_temb    = (const float*)d_in[4];
    const float* st_w1       = (const float*)d_in[5];
    const float* st_b1       = (const float*)d_in[6];
    const float* st_w2       = (const float*)d_in[7];
    const float* st_b2       = (const float*)d_in[8];
    const float* st_temb     = (const float*)d_in[9];
    const float* readout     = (const float*)d_in[10];
    const float* pos         = (const float*)d_in[11];
    const float* ln1_w       = (const float*)d_in[12];
    const float* ln1_b       = (const float*)d_in[13];
    const float* attn_w      = (const float*)d_in[14];
    const float* attn_b      = (const float*)d_in[15];
    const float* proj_w      = (const float*)d_in[16];
    const float* proj_b      = (const float*)d_in[17];
    const float* ln2_w       = (const float*)d_in[18];
    const float* ln2_b       = (const float*)d_in[19];
    const float* fc_w        = (const float*)d_in[20];
    const float* fc_b        = (const float*)d_in[21];
    const float* fc2_w       = (const float*)d_in[22];
    const float* fc2_b       = (const float*)d_in[23];
    const float* lnf_w       = (const float*)d_in[24];
    const float* lnf_b       = (const float*)d_in[25];
    float* out = (float*)d_out;

    float *x, *att, *st, *uq, *cq, *u1, *c1;
    float2 *sA, *sB;
    __half *xh, *ah, *bhp, *ph, *qb, *kb, *vb, *wq, *wp, *w1, *w2, *wi;
    cudaGetSymbolAddress((void**)&x,   g_x);
    cudaGetSymbolAddress((void**)&att, g_att);
    cudaGetSymbolAddress((void**)&st,  g_st);
    cudaGetSymbolAddress((void**)&sA,  g_sA);
    cudaGetSymbolAddress((void**)&sB,  g_sB);
    cudaGetSymbolAddress((void**)&xh,  g_xh);
    cudaGetSymbolAddress((void**)&ah,  g_ah);
    cudaGetSymbolAddress((void**)&bhp, g_bh);
    cudaGetSymbolAddress((void**)&ph,  g_ph);
    cudaGetSymbolAddress((void**)&qb,  g_q);
    cudaGetSymbolAddress((void**)&kb,  g_k);
    cudaGetSymbolAddress((void**)&vb,  g_v);
    cudaGetSymbolAddress((void**)&wq,  g_wq);
    cudaGetSymbolAddress((void**)&wp,  g_wp);
    cudaGetSymbolAddress((void**)&w1,  g_w1);
    cudaGetSymbolAddress((void**)&w2,  g_w2);
    cudaGetSymbolAddress((void**)&wi,  g_wi);
    cudaGetSymbolAddress((void**)&uq,  g_uq);
    cudaGetSymbolAddress((void**)&cq,  g_cq);
    cudaGetSymbolAddress((void**)&u1,  g_u1);
    cudaGetSymbolAddress((void**)&c1,  g_c1);

    cudaFuncSetAttribute(attn_mma, cudaFuncAttributeMaxDynamicSharedMemorySize, ATT_SMEM_BYTES);
    cudaFuncSetAttribute(gemm_mma<0>, cudaFuncAttributeMaxDynamicSharedMemorySize, GSMEM);
    cudaFuncSetAttribute(gemm_mma<3>, cudaFuncAttributeMaxDynamicSharedMemorySize, GSMEM);
    cudaFuncSetAttribute(gemm_mma<4>, cudaFuncAttributeMaxDynamicSharedMemorySize, GSMEM);
    cudaFuncSetAttribute(gemm_mma<5>, cudaFuncAttributeMaxDynamicSharedMemorySize, GSMEM);

    // ---- weight prep + LN fusion vectors ----
    wprep<<<dim3(1152/32, 384/32, 12), dim3(32, 8)>>>(attn_w, ln1_w, wq, 384, 1152);
    wprep<<<dim3(384/32,  384/32, 12), dim3(32, 8)>>>(proj_w, nullptr, wp, 384, 384);
    wprep<<<dim3(1536/32, 384/32, 12), dim3(32, 8)>>>(fc_w,  ln2_w, w1, 384, 1536);
    wprep<<<dim3(384/32, 1536/32, 12), dim3(32, 8)>>>(fc2_w, nullptr, w2, 1536, 384);
    wprep<<<dim3(384/32,  192/32, 1),  dim3(32, 8)>>>(img_proj_w, nullptr, wi, 192, 384);
    prep_uc<<<dim3(1152/128, 12), 128>>>(attn_w, ln1_w, ln1_b, attn_b, uq, cq, 1152);
    prep_uc<<<dim3(1536/128, 12), 128>>>(fc_w,  ln2_w, ln2_b, fc_b,  u1, c1, 1536);

    // ---- tokenizers ----
    st_kernel<<<BATCH * OBS_H, 384>>>(agent_state, st_w1, st_b1, st_w2, st_b2, st);
    im2col_kernel<<<(M_PATCH * PK) / 256, 256>>>(images, ph);
    gemm_mma<0><<<dim3(3, M_PATCH / 128), 128, GSMEM>>>(
        ph, wi, img_proj_b, nullptr, att, nullptr, nullptr, nullptr, nullptr,
        nullptr, nullptr, nullptr, nullptr, 384, PK);
    assemble_ln<<<M_TOK, 128>>>(att, st, readout, pos, img_temb, st_temb, x, xh, sA);

    // ---- transformer layers ----
    for (int l = 0; l < NLAYER; l++) {
        gemm_mma<4><<<dim3(9, NTOK), 128, GSMEM>>>(
            xh, wq + (size_t)l * 1152 * 384, cq + l * 1152, nullptr,
            nullptr, nullptr, qb, kb, vb, sA, nullptr, uq + l * 1152, nullptr, 1152, 384);
        attn_mma<<<BATCH * NHEAD, 256, ATT_SMEM_BYTES>>>(qb, kb, vb, ah);
        gemm_mma<5><<<dim3(3, NTOK), 128, GSMEM>>>(
            ah, wp + (size_t)l * 384 * 384, proj_b + l * 384, x,
            x, nullptr, nullptr, nullptr, nullptr, nullptr, sB, nullptr, xh, 384, 384);
        gemm_mma<3><<<dim3(12, NTOK), 128, GSMEM>>>(
            xh, w1 + (size_t)l * 1536 * 384, c1 + l * 1536, nullptr,
            nullptr, bhp, nullptr, nullptr, nullptr, sB, nullptr, u1 + l * 1536, nullptr, 1536, 384);
        gemm_mma<5><<<dim3(3, NTOK), 128, GSMEM>>>(
            bhp, w2 + (size_t)l * 384 * 1536, fc2_b + l * 384, x,
            x, nullptr, nullptr, nullptr, nullptr, nullptr, sA, nullptr, xh, 384, 1536);
    }

    lnf_kernel<<<BATCH, 128>>>(x, lnf_w, lnf_b, out);
}

// round 14
// speedup vs baseline: 1.0555x; 1.0555x over previous
#include <cuda_runtime.h>
#include <cuda_fp16.h>
#include <math.h>
#include <stdint.h>

// ---------------- problem constants ----------------
#define BATCH   128
#define OBS_H   2
#define NTOK    291
#define M_TOK   (BATCH*NTOK)   // 37248 = 291*128
#define D_EMB   384
#define NHEAD   6
#define NLAYER  12
#define N_IMG   144
#define PK      192
#define M_PATCH (BATCH*OBS_H*N_IMG)

// ---------------- scratch ----------------
__device__ float g_x  [M_TOK * D_EMB];
__device__ float g_att[M_PATCH * D_EMB];
__device__ float g_st [BATCH * OBS_H * D_EMB];
__device__ float2 g_sA[3 * M_TOK];             // row-stat partials (x)
__device__ float2 g_sB[3 * M_TOK];             // row-stat partials (after proj)
__device__ __half g_xh[M_TOK*384];
__device__ __half g_ah[M_TOK*384];
__device__ __half g_bh[M_TOK*1536];
__device__ __half g_ph[M_PATCH*192];
__device__ __half g_q [BATCH*NHEAD*NTOK*64];
__device__ __half g_k [BATCH*NHEAD*NTOK*64];
__device__ __half g_v [BATCH*NHEAD*NTOK*64];
// transposed weights [N,K] fp16 (qkv/fc1 have ln-g folded in)
__device__ __half g_wq[12*1152*384];
__device__ __half g_wp[12*384*384];
__device__ __half g_w1[12*1536*384];
__device__ __half g_w2[12*384*1536];
__device__ __half g_wi[384*192];
// LN-fusion vectors: u = g@W, c = b@W + bias
__device__ float g_uq[12*1152], g_cq[12*1152];
__device__ float g_u1[12*1536], g_c1[12*1536];

__device__ __forceinline__ float gelu_tanh(float v) {
    const float c = 0.7978845608028654f;
    float u = c * (v + 0.044715f * v * v * v);
    return 0.5f * v * (1.0f + tanhf(u));
}

__device__ __forceinline__ uint32_t smem_u32(const void* p) {
    uint32_t a;
    asm("{ .reg .u64 t; cvta.to.shared.u64 t, %1; cvt.u32.u64 %0, t; }" : "=r"(a) : "l"(p));
    return a;
}

__device__ __forceinline__ void mma16816(float c[4], const uint32_t a[4], const uint32_t b[2]) {
    asm volatile(
        "mma.sync.aligned.m16n8k16.row.col.f32.f16.f16.f32 "
        "{%0,%1,%2,%3}, {%4,%5,%6,%7}, {%8,%9}, {%0,%1,%2,%3};\n"
        : "+f"(c[0]), "+f"(c[1]), "+f"(c[2]), "+f"(c[3])
        : "r"(a[0]), "r"(a[1]), "r"(a[2]), "r"(a[3]), "r"(b[0]), "r"(b[1]));
}
#define LDMX4(r0, r1, r2, r3, addr) \
    asm volatile("ldmatrix.sync.aligned.m8n8.x4.shared.b16 {%0,%1,%2,%3}, [%4];" \
        : "=r"(r0), "=r"(r1), "=r"(r2), "=r"(r3) : "r"(addr))
#define LDMX4T(r0, r1, r2, r3, addr) \
    asm volatile("ldmatrix.sync.aligned.m8n8.x4.trans.shared.b16 {%0,%1,%2,%3}, [%4];" \
        : "=r"(r0), "=r"(r1), "=r"(r2), "=r"(r3) : "r"(addr))

// =======================================================================
// fp16 HMMA GEMM (R12 config: 256 thr, 8 warps 2x4, warp tile 64x32).
// BK=64, 3-stage cp.async pipeline, ONE sync per 64-k-tile.
// smem stage: A[128][72h] + B[128][72h], 144B rows (conflict-free), 36.9KB.
// EPI 0: +bias -> f32 C
// EPI 4: LN-fused -> scatter q/k/v fp16           (reads 3 stat partials)
// EPI 3: LN-fused + gelu -> fp16 Ch               (reads 3 stat partials)
// EPI 5: +bias+res -> f32 C, fp16 XH, stat partial (smem-reduced across warps)
// =======================================================================
#define ROWB      144
#define STAGE_B   (2*128*ROWB)        // 36864
#define GSMEM     (3*STAGE_B)         // 110592

template <int EPI>
__global__ void __launch_bounds__(256, 2) gemm_mma(
    const __half* __restrict__ A, const __half* __restrict__ B,
    const float* __restrict__ bias, const float* __restrict__ Rres,
    float* __restrict__ C, __half* __restrict__ Ch,
    __half* __restrict__ Qo, __half* __restrict__ Ko, __half* __restrict__ Vo,
    const float2* __restrict__ stats_in, float2* __restrict__ stats_out,
    const float* __restrict__ uvec, __half* __restrict__ XH,
    int N, int K)
{
    extern __shared__ __align__(16) char dyn[];
    const uint32_t sbase = smem_u32(dyn);
    const int tid = threadIdx.x, lane = tid & 31, warp = tid >> 5;
    const int wm = warp >> 2, wn = warp & 3;
    const int bn = blockIdx.x, bm = blockIdx.y;

    float acc[4][4][4];
#pragma unroll
    for (int i = 0; i < 4; i++)
#pragma unroll
        for (int j = 0; j < 4; j++)
#pragma unroll
            for (int q = 0; q < 4; q++) acc[i][j][q] = 0.f;

    const char* gsrc[2] = {
        (const char*)(A + (size_t)bm * 128 * K),
        (const char*)(B + (size_t)bn * 128 * K) };
    const size_t rs = (size_t)K * 2;

// 64-k tile: per operand 128 rows x 128B (8 chunks of 16B) = 1024 chunks
#define LOADT(t_) do { \
    uint32_t db_ = sbase + ((t_) % 3) * STAGE_B; \
    size_t go_ = (size_t)(t_) * 128; \
    _Pragma("unroll") \
    for (int b_ = 0; b_ < 2; b_++) { \
        const char* g_ = gsrc[b_]; \
        uint32_t d_ = db_ + b_ * (128 * ROWB); \
        _Pragma("unroll") \
        for (int i_ = 0; i_ < 4; i_++) { \
            int idx_ = i_ * 256 + tid; \
            int r_ = idx_ >> 3, c_ = (idx_ & 7) * 16; \
            asm volatile("cp.async.cg.shared.global [%0], [%1], 16;" \
                :: "r"(d_ + r_ * ROWB + c_), "l"(g_ + (size_t)r_ * rs + go_ + c_) : "memory"); \
        } \
    } \
    asm volatile("cp.async.commit_group;" ::: "memory"); \
} while (0)

    const int T = K >> 6;
    LOADT(0);
    if (T > 1) LOADT(1);

    for (int t = 0; t < T; t++) {
        if (t + 1 < T) asm volatile("cp.async.wait_group 1;" ::: "memory");
        else           asm volatile("cp.async.wait_group 0;" ::: "memory");
        __syncthreads();
        // issue next-next tile loads FIRST so cp.async overlaps the mma burst
        if (t + 2 < T) LOADT(t + 2);
        const uint32_t sb = sbase + (t % 3) * STAGE_B;

#pragma unroll
        for (int ks = 0; ks < 4; ks++) {
            const int k0 = ks * 16;
            uint32_t bf[4][2];
#pragma unroll
            for (int pr = 0; pr < 2; pr++) {
                int trow = wn * 32 + pr * 16 + ((lane >> 4) & 1) * 8 + (lane & 7);
                int tcol = k0 + ((lane >> 3) & 1) * 8;
                uint32_t ab = sb + 128 * ROWB + trow * ROWB + tcol * 2;
                LDMX4(bf[2*pr][0], bf[2*pr][1], bf[2*pr+1][0], bf[2*pr+1][1], ab);
            }
#pragma unroll
            for (int i = 0; i < 4; i++) {
                int arow = wm * 64 + i * 16 + (lane & 7) + ((lane >> 3) & 1) * 8;
                int acol = k0 + ((lane >> 4) & 1) * 8;
                uint32_t aa = sb + arow * ROWB + acol * 2;
                uint32_t a4[4];
                LDMX4(a4[0], a4[1], a4[2], a4[3], aa);
#pragma unroll
                for (int j = 0; j < 4; j++) mma16816(acc[i][j], a4, bf[j]);
            }
        }
    }

    // EPI==5: per-row stat reduction buffer in (now-free) pipeline smem
    float2* sstat = (float2*)dyn;
    if (EPI == 5) {
        __syncthreads();                 // everyone done reading stage smem
        if (tid < 128) sstat[tid] = make_float2(0.f, 0.f);
        __syncthreads();
    }

    const float att_scale = 1.0f / sqrtf(64.0f + 1e-8f);

#pragma unroll
    for (int i = 0; i < 4; i++) {
        int row0 = bm * 128 + wm * 64 + i * 16 + (lane >> 2);
#pragma unroll
        for (int half_ = 0; half_ < 2; half_++) {
            int row = row0 + half_ * 8;
            float mu = 0.f, inv = 1.f;
            if (EPI == 3 || EPI == 4) {
                float2 p0 = stats_in[row];
                float2 p1 = stats_in[M_TOK + row];
                float2 p2 = stats_in[2 * M_TOK + row];
                float sx = p0.x + p1.x + p2.x;
                float sq = p0.y + p1.y + p2.y;
                mu = sx * (1.0f / 384.0f);
                inv = rsqrtf(sq * (1.0f / 384.0f) - mu * mu + 1e-5f);
            }
            float rsum = 0.f, rsq = 0.f;
#pragma unroll
            for (int j = 0; j < 4; j++) {
                int col = bn * 128 + wn * 32 + j * 8 + (lane & 3) * 2;
                float a0 = acc[i][j][half_ * 2 + 0];
                float a1 = acc[i][j][half_ * 2 + 1];
                if (EPI == 0) {
                    size_t off = (size_t)row * N + col;
                    *(float2*)(C + off) = make_float2(a0 + bias[col], a1 + bias[col + 1]);
                } else if (EPI == 4) {
                    float v0 = inv * (a0 - mu * uvec[col])     + bias[col];
                    float v1 = inv * (a1 - mu * uvec[col + 1]) + bias[col + 1];
                    int kind = col / 384;
                    int hh = (col % 384) >> 6;
                    int dd = col & 63;
                    int bb = row / NTOK, tt = row % NTOK;
                    size_t o3 = ((size_t)(bb * NHEAD + hh) * NTOK + tt) * 64 + dd;
                    if (kind == 0)
                        *(__half2*)(Qo + o3) = __floats2half2_rn(v0 * att_scale, v1 * att_scale);
                    else if (kind == 1)
                        *(__half2*)(Ko + o3) = __floats2half2_rn(v0, v1);
                    else
                        *(__half2*)(Vo + o3) = __floats2half2_rn(v0, v1);
                } else if (EPI == 3) {
                    float v0 = gelu_tanh(inv * (a0 - mu * uvec[col])     + bias[col]);
                    float v1 = gelu_tanh(inv * (a1 - mu * uvec[col + 1]) + bias[col + 1]);
                    size_t off = (size_t)row * N + col;
                    *(__half2*)((char*)Ch + off * 2) = __floats2half2_rn(v0, v1);
                } else { // EPI == 5
                    size_t off = (size_t)row * N + col;
                    float2 rr = *(const float2*)(Rres + off);
                    float v0 = a0 + bias[col]     + rr.x;
                    float v1 = a1 + bias[col + 1] + rr.y;
                    *(float2*)(C + off) = make_float2(v0, v1);
                    *(__half2*)((char*)XH + off * 2) = __floats2half2_rn(v0, v1);
                    rsum += v0 + v1;
                    rsq  += v0 * v0 + v1 * v1;
                }
            }
            if (EPI == 5) {
                rsum += __shfl_xor_sync(~0u, rsum, 1); rsum += __shfl_xor_sync(~0u, rsum, 2);
                rsq  += __shfl_xor_sync(~0u, rsq, 1);  rsq  += __shfl_xor_sync(~0u, rsq, 2);
                if ((lane & 3) == 0) {
                    int rl = row - bm * 128;       // 0..127
                    atomicAdd(&sstat[rl].x, rsum);
                    atomicAdd(&sstat[rl].y, rsq);
                }
            }
        }
    }
    if (EPI == 5) {
        __syncthreads();
        if (tid < 128)
            stats_out[bn * M_TOK + bm * 128 + tid] = sstat[tid];
    }
}

// ---------------- weight transpose + fp16, optional g-fold ----
__global__ void wprep(const float* __restrict__ W, const float* __restrict__ g,
                      __half* __restrict__ Wh, int K, int N)
{
    __shared__ float t[32][33];
    const int l = blockIdx.z;
    const size_t lo = (size_t)l * K * N;
    const float* Wp = W + lo;
    const int kt = blockIdx.y * 32, nt = blockIdx.x * 32;
    const int tx = threadIdx.x, ty = threadIdx.y;
#pragma unroll
    for (int i = ty; i < 32; i += 8)
        t[i][tx] = Wp[(size_t)(kt + i) * N + nt + tx];
    __syncthreads();
    float gk = g ? g[l * K + kt + tx] : 1.0f;
#pragma unroll
    for (int i = ty; i < 32; i += 8)
        Wh[lo + (size_t)(nt + i) * K + kt + tx] = __float2half_rn(t[tx][i] * gk);
}

// ---------------- LN-fusion u/c prep ----
__global__ void prep_uc(const float* __restrict__ W, const float* __restrict__ g,
                        const float* __restrict__ b, const float* __restrict__ bias,
                        float* __restrict__ u, float* __restrict__ c, int N)
{
    const int l = blockIdx.y;
    const int n = blockIdx.x * 128 + threadIdx.x;
    const float* Wp = W + (size_t)l * 384 * N + n;
    const float* gp = g + l * 384;
    const float* bp = b + l * 384;
    float su = 0.f, sc = 0.f;
    for (int k = 0; k < 384; k++) {
        float w = Wp[(size_t)k * N];
        su = fmaf(gp[k], w, su);
        sc = fmaf(bp[k], w, sc);
    }
    u[l * N + n] = su;
    c[l * N + n] = sc + bias[l * N + n];
}

__global__ void lnf_kernel(const float* __restrict__ x, const float* __restrict__ w,
                           const float* __restrict__ b, float* __restrict__ out)
{
    size_t bi = blockIdx.x;
    const float* xr = x + (bi * NTOK + (NTOK - 1)) * D_EMB;
    int tid = threadIdx.x;
    float v0 = xr[tid], v1 = xr[tid + 128], v2 = xr[tid + 256];
    float s = v0 + v1 + v2, sq = v0*v0 + v1*v1 + v2*v2;
#pragma unroll
    for (int o = 16; o; o >>= 1) {
        s  += __shfl_xor_sync(~0u, s,  o);
        sq += __shfl_xor_sync(~0u, sq, o);
    }
    __shared__ float ws[4], wq[4], red[2];
    int warp = tid >> 5, lane = tid & 31;
    if (!lane) { ws[warp] = s; wq[warp] = sq; }
    __syncthreads();
    if (tid == 0) {
        float S = ws[0]+ws[1]+ws[2]+ws[3], Q = wq[0]+wq[1]+wq[2]+wq[3];
        float mean = S * (1.0f / 384.0f);
        red[0] = mean;
        red[1] = rsqrtf(Q * (1.0f / 384.0f) - mean * mean + 1e-5f);
    }
    __syncthreads();
    float mean = red[0], inv = red[1];
    out[bi * D_EMB + tid]       = (v0 - mean) * inv * w[tid]       + b[tid];
    out[bi * D_EMB + tid + 128] = (v1 - mean) * inv * w[tid + 128] + b[tid + 128];
    out[bi * D_EMB + tid + 256] = (v2 - mean) * inv * w[tid + 256] + b[tid + 256];
}

// ---------------- Flash attention on HMMA (fp32 softmax) ----------------
// grid (BH, 2): blockIdx.y splits q-tiles 0-9 / 10-18 -> max 2 tiles/warp.
// K and V row-major [320][72h]; V B-fragments via ldmatrix.trans.
#define KPAD 320
#define KSTR 72
#define ATT_SMEM_HALVES (2*KPAD*KSTR)
#define ATT_SMEM_BYTES  (ATT_SMEM_HALVES * 2)    // 92160

__global__ void __launch_bounds__(256, 2) attn_mma(
    const __half* __restrict__ Qb, const __half* __restrict__ Kb,
    const __half* __restrict__ Vb, __half* __restrict__ oh)
{
    extern __shared__ __half smh[];
    __half* Ks = smh;
    __half* Vs = smh + KPAD * KSTR;

    const int bh = blockIdx.x;
    const int b = bh / NHEAD, h = bh % NHEAD;
    const int tid = threadIdx.x, warp = tid >> 5, lane = tid & 31;
    const size_t ib = (size_t)bh * NTOK * 64;
    const int tstart = blockIdx.y * 10;
    const int tend = (blockIdx.y == 0) ? 10 : 19;

    // fill K and V rows 0..290; zero V pad rows 291..319 (NaN*0 hazard in P@V)
    for (int idx = tid; idx < NTOK * 8; idx += 256) {
        int t = idx >> 3, s = idx & 7;
        ((int4*)(Ks + t * KSTR))[s] = ((const int4*)(Kb + ib + (size_t)t * 64))[s];
        ((int4*)(Vs + t * KSTR))[s] = ((const int4*)(Vb + ib + (size_t)t * 64))[s];
    }
    for (int idx = tid; idx < (KPAD - NTOK) * 8; idx += 256) {
        int t = NTOK + (idx >> 3), s = idx & 7;
        ((int4*)(Vs + t * KSTR))[s] = make_int4(0, 0, 0, 0);
    }
    __syncthreads();

    const uint32_t ks0 = smem_u32(Ks), vs0 = smem_u32(Vs);

    for (int tile = tstart + warp; tile < tend; tile += 8) {
        // ---- Q fragments straight from gmem (canonical m16n8k16 A layout) ----
        uint32_t qf[4][4];
        {
            int r0g = tile * 16 + (lane >> 2);
            int r1g = r0g + 8;
            if (r0g >= NTOK) r0g = NTOK - 1;
            if (r1g >= NTOK) r1g = NTOK - 1;
            const __half* Q0 = Qb + ib + (size_t)r0g * 64;
            const __half* Q1 = Qb + ib + (size_t)r1g * 64;
            int c0 = (lane & 3) * 2;
#pragma unroll
            for (int ks = 0; ks < 4; ks++) {
                qf[ks][0] = *(const uint32_t*)(Q0 + ks * 16 + c0);
                qf[ks][1] = *(const uint32_t*)(Q1 + ks * 16 + c0);
                qf[ks][2] = *(const uint32_t*)(Q0 + ks * 16 + c0 + 8);
                qf[ks][3] = *(const uint32_t*)(Q1 + ks * 16 + c0 + 8);
            }
        }
        float O[8][4];
#pragma unroll
        for (int j = 0; j < 8; j++)
#pragma unroll
            for (int q = 0; q < 4; q++) O[j][q] = 0.f;
        float mr0 = -1e30f, mr1 = -1e30f, lr0 = 0.f, lr1 = 0.f;

        for (int ch = 0; ch < 5; ch++) {
            float S[8][4];
#pragma unroll
            for (int j = 0; j < 8; j++)
#pragma unroll
                for (int q = 0; q < 4; q++) S[j][q] = 0.f;

#pragma unroll
            for (int ks = 0; ks < 4; ks++) {
#pragma unroll
                for (int kg = 0; kg < 4; kg++) {
                    int trow = ch * 64 + kg * 16 + ((lane >> 4) & 1) * 8 + (lane & 7);
                    int tcol = ks * 16 + ((lane >> 3) & 1) * 8;
                    uint32_t ad = ks0 + (trow * KSTR + tcol) * 2;
                    uint32_t bfr[4];
                    LDMX4(bfr[0], bfr[1], bfr[2], bfr[3], ad);
                    mma16816(S[kg * 2],     qf[ks], bfr);
                    mma16816(S[kg * 2 + 1], qf[ks], bfr + 2);
                }
            }

            float cm0 = -1e30f, cm1 = -1e30f;
#pragma unroll
            for (int j = 0; j < 8; j++) {
                int k0c = ch * 64 + j * 8 + (lane & 3) * 2;
                if (k0c >= NTOK)     { S[j][0] = -1e30f; S[j][2] = -1e30f; }
                if (k0c + 1 >= NTOK) { S[j][1] = -1e30f; S[j][3] = -1e30f; }
                cm0 = fmaxf(cm0, fmaxf(S[j][0], S[j][1]));
                cm1 = fmaxf(cm1, fmaxf(S[j][2], S[j][3]));
            }
            cm0 = fmaxf(cm0, __shfl_xor_sync(~0u, cm0, 1));
            cm0 = fmaxf(cm0, __shfl_xor_sync(~0u, cm0, 2));
            cm1 = fmaxf(cm1, __shfl_xor_sync(~0u, cm1, 1));
            cm1 = fmaxf(cm1, __shfl_xor_sync(~0u, cm1, 2));

            float mn0 = fmaxf(mr0, cm0), mn1 = fmaxf(mr1, cm1);
            float sc0 = __expf(mr0 - mn0), sc1 = __expf(mr1 - mn1);

            float cs0 = 0.f, cs1 = 0.f;
            uint32_t pf[4][4];
#pragma unroll
            for (int j = 0; j < 8; j++) {
                float e0 = __expf(S[j][0] - mn0), e1 = __expf(S[j][1] - mn0);
                float e2 = __expf(S[j][2] - mn1), e3 = __expf(S[j][3] - mn1);
                cs0 += e0 + e1; cs1 += e2 + e3;
                __half2 p01 = __floats2half2_rn(e0, e1);
                __half2 p23 = __floats2half2_rn(e2, e3);
                int jg = j >> 1, sl = (j & 1) * 2;
                pf[jg][sl]     = reinterpret_cast<uint32_t&>(p01);
                pf[jg][sl + 1] = reinterpret_cast<uint32_t&>(p23);
            }
            cs0 += __shfl_xor_sync(~0u, cs0, 1); cs0 += __shfl_xor_sync(~0u, cs0, 2);
            cs1 += __shfl_xor_sync(~0u, cs1, 1); cs1 += __shfl_xor_sync(~0u, cs1, 2);
            lr0 = lr0 * sc0 + cs0; lr1 = lr1 * sc1 + cs1;
            mr0 = mn0; mr1 = mn1;
#pragma unroll
            for (int j = 0; j < 8; j++) {
                O[j][0] *= sc0; O[j][1] *= sc0; O[j][2] *= sc1; O[j][3] *= sc1;
            }

            // ---- O += P @ V : V row-major, B-fragments via ldmatrix.trans ----
#pragma unroll
            for (int jg = 0; jg < 4; jg++) {
#pragma unroll
                for (int dg = 0; dg < 4; dg++) {
                    int trow = ch * 64 + jg * 16 + ((lane >> 3) & 1) * 8 + (lane & 7);
                    int tcol = dg * 16 + ((lane >> 4) & 1) * 8;
                    uint32_t ad = vs0 + (trow * KSTR + tcol) * 2;
                    uint32_t bfr[4];
                    LDMX4T(bfr[0], bfr[1], bfr[2], bfr[3], ad);
                    mma16816(O[dg * 2],     pf[jg], bfr);
                    mma16816(O[dg * 2 + 1], pf[jg], bfr + 2);
                }
            }
        }

        float inv0 = 1.0f / lr0, inv1 = 1.0f / lr1;
        int r0 = tile * 16 + (lane >> 2), r1 = r0 + 8;
#pragma unroll
        for (int j = 0; j < 8; j++) {
            int d = j * 8 + (lane & 3) * 2;
            if (r0 < NTOK) {
                __half2 hv = (r0 == NTOK - 1)
                    ? *(const __half2*)(Vb + ib + (size_t)(NTOK - 1) * 64 + d)
                    : __floats2half2_rn(O[j][0] * inv0, O[j][1] * inv0);
                *(__half2*)(oh + ((size_t)b * NTOK + r0) * D_EMB + h * 64 + d) = hv;
            }
            if (r1 < NTOK) {
                __half2 hv = (r1 == NTOK - 1)
                    ? *(const __half2*)(Vb + ib + (size_t)(NTOK - 1) * 64 + d)
                    : __floats2half2_rn(O[j][2] * inv1, O[j][3] * inv1);
                *(__half2*)(oh + ((size_t)b * NTOK + r1) * D_EMB + h * 64 + d) = hv;
            }
        }
    }
}

// ---------------- tokenizers ----------------
__global__ void st_kernel(const float* __restrict__ as, const float* __restrict__ w1,
                          const float* __restrict__ b1, const float* __restrict__ w2,
                          const float* __restrict__ b2, float* __restrict__ st)
{
    __shared__ float h1[32];
    int bt = blockIdx.x;
    int tid = threadIdx.x;
    float s0 = as[bt * 2], s1 = as[bt * 2 + 1];
    if (tid < 32) {
        float v = b1[tid] + s0 * w1[tid] + s1 * w1[32 + tid];
        h1[tid] = v > 0.f ? v : 0.f;
    }
    __syncthreads();
    float acc = b2[tid];
#pragma unroll
    for (int k = 0; k < 32; k++) acc = fmaf(h1[k], w2[k * 384 + tid], acc);
    st[(size_t)bt * 384 + tid] = acc;
}

__global__ void im2col_kernel(const float* __restrict__ img, __half* __restrict__ ph)
{
    int idx = blockIdx.x * 256 + threadIdx.x;
    int f = idx % 192;
    int rem = idx / 192;
    int pidx = rem % 144;
    int bt = rem / 144;
    int pr = f / 24, pc = (f % 24) / 3, c = f % 3;
    int hp = pidx / 12, wp = pidx % 12;
    ph[idx] = __float2half_rn(img[(((size_t)bt * 3 + c) * 96 + hp * 8 + pr) * 96 + wp * 8 + pc]);
}

// assemble residual stream + xh + stat partials (block per row, 128 thr)
__global__ void assemble_ln(const float* __restrict__ imgtok, const float* __restrict__ st,
                            const float* __restrict__ readout, const float* __restrict__ pos,
                            const float* __restrict__ img_temb, const float* __restrict__ st_temb,
                            float* __restrict__ x, __half* __restrict__ xh,
                            float2* __restrict__ stats)
{
    size_t row = blockIdx.x;
    int tok = (int)(row % NTOK);
    int b = (int)(row / NTOK);
    int tid = threadIdx.x;
    float v[3];
#pragma unroll
    for (int q = 0; q < 3; q++) {
        int d = tid + q * 128;
        float vv;
        if (tok == NTOK - 1) {
            vv = readout[d];
        } else {
            int t = tok / 145, r = tok % 145;
            if (r == 0) vv = st[((size_t)(b * 2 + t)) * 384 + d] + st_temb[t * 384 + d];
            else        vv = imgtok[((size_t)(b * 2 + t) * 144 + (r - 1)) * 384 + d] + img_temb[t * 384 + d];
        }
        vv += pos[tok * 384 + d];
        v[q] = vv;
        x[row * D_EMB + d] = vv;
        xh[row * D_EMB + d] = __float2half_rn(vv);
    }
    float s = v[0] + v[1] + v[2], sq = v[0]*v[0] + v[1]*v[1] + v[2]*v[2];
#pragma unroll
    for (int o = 16; o; o >>= 1) {
        s  += __shfl_xor_sync(~0u, s,  o);
        sq += __shfl_xor_sync(~0u, sq, o);
    }
    __shared__ float ws[4], wq[4];
    int warp = tid >> 5, lane = tid & 31;
    if (!lane) { ws[warp] = s; wq[warp] = sq; }
    __syncthreads();
    if (tid == 0) {
        stats[row] = make_float2(ws[0]+ws[1]+ws[2]+ws[3], wq[0]+wq[1]+wq[2]+wq[3]);
        stats[M_TOK + row] = make_float2(0.f, 0.f);
        stats[2 * M_TOK + row] = make_float2(0.f, 0.f);
    }
}

// ---------------- launch ----------------
extern "C" void kernel_launch(void* const* d_in, const int* in_sizes, int n_in,
                              void* d_out, int out_size)
{
    const float* images      = (const float*)d_in[0];
    const float* agent_state = (const float*)d_in[1];
    const float* img_proj_w  = (const float*)d_in[2];
    const float* img_proj_b  = (const float*)d_in[3];
    const float* img_temb    = (const float*)d_in[4];
    const float* st_w1       = (const float*)d_in[5];
    const float* st_b1       = (const float*)d_in[6];
    const float* st_w2       = (const float*)d_in[7];
    const float* st_b2       = (const float*)d_in[8];
    const float* st_temb     = (const float*)d_in[9];
    const float* readout     = (const float*)d_in[10];
    const float* pos         = (const float*)d_in[11];
    const float* ln1_w       = (const float*)d_in[12];
    const float* ln1_b       = (const float*)d_in[13];
    const float* attn_w      = (const float*)d_in[14];
    const float* attn_b      = (const float*)d_in[15];
    const float* proj_w      = (const float*)d_in[16];
    const float* proj_b      = (const float*)d_in[17];
    const float* ln2_w       = (const float*)d_in[18];
    const float* ln2_b       = (const float*)d_in[19];
    const float* fc_w        = (const float*)d_in[20];
    const float* fc_b        = (const float*)d_in[21];
    const float* fc2_w       = (const float*)d_in[22];
    const float* fc2_b       = (const float*)d_in[23];
    const float* lnf_w       = (const float*)d_in[24];
    const float* lnf_b       = (const float*)d_in[25];
    float* out = (float*)d_out;

    float *x, *att, *st, *uq, *cq, *u1, *c1;
    float2 *sA, *sB;
    __half *xh, *ah, *bhp, *ph, *qb, *kb, *vb, *wq, *wp, *w1, *w2, *wi;
    cudaGetSymbolAddress((void**)&x,   g_x);
    cudaGetSymbolAddress((void**)&att, g_att);
    cudaGetSymbolAddress((void**)&st,  g_st);
    cudaGetSymbolAddress((void**)&sA,  g_sA);
    cudaGetSymbolAddress((void**)&sB,  g_sB);
    cudaGetSymbolAddress((void**)&xh,  g_xh);
    cudaGetSymbolAddress((void**)&ah,  g_ah);
    cudaGetSymbolAddress((void**)&bhp, g_bh);
    cudaGetSymbolAddress((void**)&ph,  g_ph);
    cudaGetSymbolAddress((void**)&qb,  g_q);
    cudaGetSymbolAddress((void**)&kb,  g_k);
    cudaGetSymbolAddress((void**)&vb,  g_v);
    cudaGetSymbolAddress((void**)&wq,  g_wq);
    cudaGetSymbolAddress((void**)&wp,  g_wp);
    cudaGetSymbolAddress((void**)&w1,  g_w1);
    cudaGetSymbolAddress((void**)&w2,  g_w2);
    cudaGetSymbolAddress((void**)&wi,  g_wi);
    cudaGetSymbolAddress((void**)&uq,  g_uq);
    cudaGetSymbolAddress((void**)&cq,  g_cq);
    cudaGetSymbolAddress((void**)&u1,  g_u1);
    cudaGetSymbolAddress((void**)&c1,  g_c1);

    cudaFuncSetAttribute(attn_mma, cudaFuncAttributeMaxDynamicSharedMemorySize, ATT_SMEM_BYTES);
    cudaFuncSetAttribute(gemm_mma<0>, cudaFuncAttributeMaxDynamicSharedMemorySize, GSMEM);
    cudaFuncSetAttribute(gemm_mma<3>, cudaFuncAttributeMaxDynamicSharedMemorySize, GSMEM);
    cudaFuncSetAttribute(gemm_mma<4>, cudaFuncAttributeMaxDynamicSharedMemorySize, GSMEM);
    cudaFuncSetAttribute(gemm_mma<5>, cudaFuncAttributeMaxDynamicSharedMemorySize, GSMEM);

    // ---- weight prep + LN fusion vectors ----
    wprep<<<dim3(1152/32, 384/32, 12), dim3(32, 8)>>>(attn_w, ln1_w, wq, 384, 1152);
    wprep<<<dim3(384/32,  384/32, 12), dim3(32, 8)>>>(proj_w, nullptr, wp, 384, 384);
    wprep<<<dim3(1536/32, 384/32, 12), dim3(32, 8)>>>(fc_w,  ln2_w, w1, 384, 1536);
    wprep<<<dim3(384/32, 1536/32, 12), dim3(32, 8)>>>(fc2_w, nullptr, w2, 1536, 384);
    wprep<<<dim3(384/32,  192/32, 1),  dim3(32, 8)>>>(img_proj_w, nullptr, wi, 192, 384);
    prep_uc<<<dim3(1152/128, 12), 128>>>(attn_w, ln1_w, ln1_b, attn_b, uq, cq, 1152);
    prep_uc<<<dim3(1536/128, 12), 128>>>(fc_w,  ln2_w, ln2_b, fc_b,  u1, c1, 1536);

    // ---- tokenizers ----
    st_kernel<<<BATCH * OBS_H, 384>>>(agent_state, st_w1, st_b1, st_w2, st_b2, st);
    im2col_kernel<<<(M_PATCH * PK) / 256, 256>>>(images, ph);
    gemm_mma<0><<<dim3(3, M_PATCH / 128), 256, GSMEM>>>(
        ph, wi, img_proj_b, nullptr, att, nullptr, nullptr, nullptr, nullptr,
        nullptr, nullptr, nullptr, nullptr, 384, PK);
    assemble_ln<<<M_TOK, 128>>>(att, st, readout, pos, img_temb, st_temb, x, xh, sA);

    // ---- transformer layers ----
    for (int l = 0; l < NLAYER; l++) {
        gemm_mma<4><<<dim3(9, NTOK), 256, GSMEM>>>(
            xh, wq + (size_t)l * 1152 * 384, cq + l * 1152, nullptr,
            nullptr, nullptr, qb, kb, vb, sA, nullptr, uq + l * 1152, nullptr, 1152, 384);
        attn_mma<<<dim3(BATCH * NHEAD, 2), 256, ATT_SMEM_BYTES>>>(qb, kb, vb, ah);
        gemm_mma<5><<<dim3(3, NTOK), 256, GSMEM>>>(
            ah, wp + (size_t)l * 384 * 384, proj_b + l * 384, x,
            x, nullptr, nullptr, nullptr, nullptr, nullptr, sB, nullptr, xh, 384, 384);
        gemm_mma<3><<<dim3(12, NTOK), 256, GSMEM>>>(
            xh, w1 + (size_t)l * 1536 * 384, c1 + l * 1536, nullptr,
            nullptr, bhp, nullptr, nullptr, nullptr, sB, nullptr, u1 + l * 1536, nullptr, 1536, 384);
        gemm_mma<5><<<dim3(3, NTOK), 256, GSMEM>>>(
            bhp, w2 + (size_t)l * 384 * 1536, fc2_b + l * 384, x,
            x, nullptr, nullptr, nullptr, nullptr, nullptr, sA, nullptr, xh, 384, 1536);
    }

    lnf_kernel<<<BATCH, 128>>>(x, lnf_w, lnf_b, out);
}

// round 15
// speedup vs baseline: 1.0963x; 1.0386x over previous
#include <cuda_runtime.h>
#include <cuda_fp16.h>
#include <math.h>
#include <stdint.h>

// ---------------- problem constants ----------------
#define BATCH   128
#define OBS_H   2
#define NTOK    291
#define M_TOK   (BATCH*NTOK)   // 37248 = 291*128
#define D_EMB   384
#define NHEAD   6
#define NLAYER  12
#define N_IMG   144
#define PK      192
#define M_PATCH (BATCH*OBS_H*N_IMG)

// ---------------- scratch ----------------
__device__ float g_x  [M_TOK * D_EMB];
__device__ float g_att[M_PATCH * D_EMB];
__device__ float g_st [BATCH * OBS_H * D_EMB];
__device__ float2 g_sA[3 * M_TOK];             // row-stat partials (x)
__device__ float2 g_sB[3 * M_TOK];             // row-stat partials (after proj)
__device__ __half g_xh[M_TOK*384];
__device__ __half g_ah[M_TOK*384];
__device__ __half g_bh[M_TOK*1536];
__device__ __half g_ph[M_PATCH*192];
__device__ __half g_q [BATCH*NHEAD*NTOK*64];
__device__ __half g_k [BATCH*NHEAD*NTOK*64];
__device__ __half g_v [BATCH*NHEAD*NTOK*64];
// transposed weights [N,K] fp16 (qkv/fc1 have ln-g folded in)
__device__ __half g_wq[12*1152*384];
__device__ __half g_wp[12*384*384];
__device__ __half g_w1[12*1536*384];
__device__ __half g_w2[12*384*1536];
__device__ __half g_wi[384*192];
// LN-fusion vectors: u = g@W, c = b@W + bias
__device__ float g_uq[12*1152], g_cq[12*1152];
__device__ float g_u1[12*1536], g_c1[12*1536];

__device__ __forceinline__ float gelu_tanh(float v) {
    const float c = 0.7978845608028654f;
    float u = c * (v + 0.044715f * v * v * v);
    return 0.5f * v * (1.0f + tanhf(u));
}

__device__ __forceinline__ uint32_t smem_u32(const void* p) {
    uint32_t a;
    asm("{ .reg .u64 t; cvta.to.shared.u64 t, %1; cvt.u32.u64 %0, t; }" : "=r"(a) : "l"(p));
    return a;
}

__device__ __forceinline__ void mma16816(float c[4], const uint32_t a[4], const uint32_t b[2]) {
    asm volatile(
        "mma.sync.aligned.m16n8k16.row.col.f32.f16.f16.f32 "
        "{%0,%1,%2,%3}, {%4,%5,%6,%7}, {%8,%9}, {%0,%1,%2,%3};\n"
        : "+f"(c[0]), "+f"(c[1]), "+f"(c[2]), "+f"(c[3])
        : "r"(a[0]), "r"(a[1]), "r"(a[2]), "r"(a[3]), "r"(b[0]), "r"(b[1]));
}
#define LDMX4(r0, r1, r2, r3, addr) \
    asm volatile("ldmatrix.sync.aligned.m8n8.x4.shared.b16 {%0,%1,%2,%3}, [%4];" \
        : "=r"(r0), "=r"(r1), "=r"(r2), "=r"(r3) : "r"(addr))
#define LDMX4T(r0, r1, r2, r3, addr) \
    asm volatile("ldmatrix.sync.aligned.m8n8.x4.trans.shared.b16 {%0,%1,%2,%3}, [%4];" \
        : "=r"(r0), "=r"(r1), "=r"(r2), "=r"(r3) : "r"(addr))

// =======================================================================
// fp16 HMMA GEMM (R12 optimum: 256 thr, 8 warps 2x4, warp tile 64x32).
// BK=64, 3-stage cp.async pipeline, ONE sync per 64-k-tile.
// smem stage: A[128][72h] + B[128][72h], 144B rows (conflict-free), 36.9KB.
// EPI 0: +bias -> f32 C
// EPI 4: LN-fused -> scatter q/k/v fp16           (reads 3 stat partials)
// EPI 3: LN-fused + gelu -> fp16 Ch               (reads 3 stat partials)
// EPI 5: +bias+res -> f32 C, fp16 XH, stat partial (smem-reduced across warps)
// =======================================================================
#define ROWB      144
#define STAGE_B   (2*128*ROWB)        // 36864
#define GSMEM     (3*STAGE_B)         // 110592

template <int EPI>
__global__ void __launch_bounds__(256, 2) gemm_mma(
    const __half* __restrict__ A, const __half* __restrict__ B,
    const float* __restrict__ bias, const float* __restrict__ Rres,
    float* __restrict__ C, __half* __restrict__ Ch,
    __half* __restrict__ Qo, __half* __restrict__ Ko, __half* __restrict__ Vo,
    const float2* __restrict__ stats_in, float2* __restrict__ stats_out,
    const float* __restrict__ uvec, __half* __restrict__ XH,
    int N, int K)
{
    extern __shared__ __align__(16) char dyn[];
    const uint32_t sbase = smem_u32(dyn);
    const int tid = threadIdx.x, lane = tid & 31, warp = tid >> 5;
    const int wm = warp >> 2, wn = warp & 3;
    const int bn = blockIdx.x, bm = blockIdx.y;

    float acc[4][4][4];
#pragma unroll
    for (int i = 0; i < 4; i++)
#pragma unroll
        for (int j = 0; j < 4; j++)
#pragma unroll
            for (int q = 0; q < 4; q++) acc[i][j][q] = 0.f;

    const char* gsrc[2] = {
        (const char*)(A + (size_t)bm * 128 * K),
        (const char*)(B + (size_t)bn * 128 * K) };
    const size_t rs = (size_t)K * 2;

#define LOADT(t_) do { \
    uint32_t db_ = sbase + ((t_) % 3) * STAGE_B; \
    size_t go_ = (size_t)(t_) * 128; \
    _Pragma("unroll") \
    for (int b_ = 0; b_ < 2; b_++) { \
        const char* g_ = gsrc[b_]; \
        uint32_t d_ = db_ + b_ * (128 * ROWB); \
        _Pragma("unroll") \
        for (int i_ = 0; i_ < 4; i_++) { \
            int idx_ = i_ * 256 + tid; \
            int r_ = idx_ >> 3, c_ = (idx_ & 7) * 16; \
            asm volatile("cp.async.cg.shared.global [%0], [%1], 16;" \
                :: "r"(d_ + r_ * ROWB + c_), "l"(g_ + (size_t)r_ * rs + go_ + c_) : "memory"); \
        } \
    } \
    asm volatile("cp.async.commit_group;" ::: "memory"); \
} while (0)

    const int T = K >> 6;
    LOADT(0);
    if (T > 1) LOADT(1);

    for (int t = 0; t < T; t++) {
        if (t + 1 < T) asm volatile("cp.async.wait_group 1;" ::: "memory");
        else           asm volatile("cp.async.wait_group 0;" ::: "memory");
        __syncthreads();
        // issue next-next tile loads FIRST so cp.async overlaps the mma burst
        if (t + 2 < T) LOADT(t + 2);
        const uint32_t sb = sbase + (t % 3) * STAGE_B;

#pragma unroll
        for (int ks = 0; ks < 4; ks++) {
            const int k0 = ks * 16;
            uint32_t bf[4][2];
#pragma unroll
            for (int pr = 0; pr < 2; pr++) {
                int trow = wn * 32 + pr * 16 + ((lane >> 4) & 1) * 8 + (lane & 7);
                int tcol = k0 + ((lane >> 3) & 1) * 8;
                uint32_t ab = sb + 128 * ROWB + trow * ROWB + tcol * 2;
                LDMX4(bf[2*pr][0], bf[2*pr][1], bf[2*pr+1][0], bf[2*pr+1][1], ab);
            }
#pragma unroll
            for (int i = 0; i < 4; i++) {
                int arow = wm * 64 + i * 16 + (lane & 7) + ((lane >> 3) & 1) * 8;
                int acol = k0 + ((lane >> 4) & 1) * 8;
                uint32_t aa = sb + arow * ROWB + acol * 2;
                uint32_t a4[4];
                LDMX4(a4[0], a4[1], a4[2], a4[3], aa);
#pragma unroll
                for (int j = 0; j < 4; j++) mma16816(acc[i][j], a4, bf[j]);
            }
        }
    }

    // EPI==5: per-row stat reduction buffer in (now-free) pipeline smem
    float2* sstat = (float2*)dyn;
    if (EPI == 5) {
        __syncthreads();                 // everyone done reading stage smem
        if (tid < 128) sstat[tid] = make_float2(0.f, 0.f);
        __syncthreads();
    }

    const float att_scale = 1.0f / sqrtf(64.0f + 1e-8f);

#pragma unroll
    for (int i = 0; i < 4; i++) {
        int row0 = bm * 128 + wm * 64 + i * 16 + (lane >> 2);
#pragma unroll
        for (int half_ = 0; half_ < 2; half_++) {
            int row = row0 + half_ * 8;
            float mu = 0.f, inv = 1.f;
            if (EPI == 3 || EPI == 4) {
                float2 p0 = stats_in[row];
                float2 p1 = stats_in[M_TOK + row];
                float2 p2 = stats_in[2 * M_TOK + row];
                float sx = p0.x + p1.x + p2.x;
                float sq = p0.y + p1.y + p2.y;
                mu = sx * (1.0f / 384.0f);
                inv = rsqrtf(sq * (1.0f / 384.0f) - mu * mu + 1e-5f);
            }
            float rsum = 0.f, rsq = 0.f;
#pragma unroll
            for (int j = 0; j < 4; j++) {
                int col = bn * 128 + wn * 32 + j * 8 + (lane & 3) * 2;
                float a0 = acc[i][j][half_ * 2 + 0];
                float a1 = acc[i][j][half_ * 2 + 1];
                if (EPI == 0) {
                    size_t off = (size_t)row * N + col;
                    *(float2*)(C + off) = make_float2(a0 + bias[col], a1 + bias[col + 1]);
                } else if (EPI == 4) {
                    float v0 = inv * (a0 - mu * uvec[col])     + bias[col];
                    float v1 = inv * (a1 - mu * uvec[col + 1]) + bias[col + 1];
                    int kind = col / 384;
                    int hh = (col % 384) >> 6;
                    int dd = col & 63;
                    int bb = row / NTOK, tt = row % NTOK;
                    size_t o3 = ((size_t)(bb * NHEAD + hh) * NTOK + tt) * 64 + dd;
                    if (kind == 0)
                        *(__half2*)(Qo + o3) = __floats2half2_rn(v0 * att_scale, v1 * att_scale);
                    else if (kind == 1)
                        *(__half2*)(Ko + o3) = __floats2half2_rn(v0, v1);
                    else
                        *(__half2*)(Vo + o3) = __floats2half2_rn(v0, v1);
                } else if (EPI == 3) {
                    float v0 = gelu_tanh(inv * (a0 - mu * uvec[col])     + bias[col]);
                    float v1 = gelu_tanh(inv * (a1 - mu * uvec[col + 1]) + bias[col + 1]);
                    size_t off = (size_t)row * N + col;
                    *(__half2*)((char*)Ch + off * 2) = __floats2half2_rn(v0, v1);
                } else { // EPI == 5
                    size_t off = (size_t)row * N + col;
                    float2 rr = *(const float2*)(Rres + off);
                    float v0 = a0 + bias[col]     + rr.x;
                    float v1 = a1 + bias[col + 1] + rr.y;
                    *(float2*)(C + off) = make_float2(v0, v1);
                    *(__half2*)((char*)XH + off * 2) = __floats2half2_rn(v0, v1);
                    rsum += v0 + v1;
                    rsq  += v0 * v0 + v1 * v1;
                }
            }
            if (EPI == 5) {
                rsum += __shfl_xor_sync(~0u, rsum, 1); rsum += __shfl_xor_sync(~0u, rsum, 2);
                rsq  += __shfl_xor_sync(~0u, rsq, 1);  rsq  += __shfl_xor_sync(~0u, rsq, 2);
                if ((lane & 3) == 0) {
                    int rl = row - bm * 128;       // 0..127
                    atomicAdd(&sstat[rl].x, rsum);
                    atomicAdd(&sstat[rl].y, rsq);
                }
            }
        }
    }
    if (EPI == 5) {
        __syncthreads();
        if (tid < 128)
            stats_out[bn * M_TOK + bm * 128 + tid] = sstat[tid];
    }
}

// ---------------- weight transpose + fp16, optional g-fold ----
__global__ void wprep(const float* __restrict__ W, const float* __restrict__ g,
                      __half* __restrict__ Wh, int K, int N)
{
    __shared__ float t[32][33];
    const int l = blockIdx.z;
    const size_t lo = (size_t)l * K * N;
    const float* Wp = W + lo;
    const int kt = blockIdx.y * 32, nt = blockIdx.x * 32;
    const int tx = threadIdx.x, ty = threadIdx.y;
#pragma unroll
    for (int i = ty; i < 32; i += 8)
        t[i][tx] = Wp[(size_t)(kt + i) * N + nt + tx];
    __syncthreads();
    float gk = g ? g[l * K + kt + tx] : 1.0f;
#pragma unroll
    for (int i = ty; i < 32; i += 8)
        Wh[lo + (size_t)(nt + i) * K + kt + tx] = __float2half_rn(t[tx][i] * gk);
}

// ---------------- LN-fusion u/c prep ----
__global__ void prep_uc(const float* __restrict__ W, const float* __restrict__ g,
                        const float* __restrict__ b, const float* __restrict__ bias,
                        float* __restrict__ u, float* __restrict__ c, int N)
{
    const int l = blockIdx.y;
    const int n = blockIdx.x * 128 + threadIdx.x;
    const float* Wp = W + (size_t)l * 384 * N + n;
    const float* gp = g + l * 384;
    const float* bp = b + l * 384;
    float su = 0.f, sc = 0.f;
    for (int k = 0; k < 384; k++) {
        float w = Wp[(size_t)k * N];
        su = fmaf(gp[k], w, su);
        sc = fmaf(bp[k], w, sc);
    }
    u[l * N + n] = su;
    c[l * N + n] = sc + bias[l * N + n];
}

__global__ void lnf_kernel(const float* __restrict__ x, const float* __restrict__ w,
                           const float* __restrict__ b, float* __restrict__ out)
{
    size_t bi = blockIdx.x;
    const float* xr = x + (bi * NTOK + (NTOK - 1)) * D_EMB;
    int tid = threadIdx.x;
    float v0 = xr[tid], v1 = xr[tid + 128], v2 = xr[tid + 256];
    float s = v0 + v1 + v2, sq = v0*v0 + v1*v1 + v2*v2;
#pragma unroll
    for (int o = 16; o; o >>= 1) {
        s  += __shfl_xor_sync(~0u, s,  o);
        sq += __shfl_xor_sync(~0u, sq, o);
    }
    __shared__ float ws[4], wq[4], red[2];
    int warp = tid >> 5, lane = tid & 31;
    if (!lane) { ws[warp] = s; wq[warp] = sq; }
    __syncthreads();
    if (tid == 0) {
        float S = ws[0]+ws[1]+ws[2]+ws[3], Q = wq[0]+wq[1]+wq[2]+wq[3];
        float mean = S * (1.0f / 384.0f);
        red[0] = mean;
        red[1] = rsqrtf(Q * (1.0f / 384.0f) - mean * mean + 1e-5f);
    }
    __syncthreads();
    float mean = red[0], inv = red[1];
    out[bi * D_EMB + tid]       = (v0 - mean) * inv * w[tid]       + b[tid];
    out[bi * D_EMB + tid + 128] = (v1 - mean) * inv * w[tid + 128] + b[tid + 128];
    out[bi * D_EMB + tid + 256] = (v2 - mean) * inv * w[tid + 256] + b[tid + 256];
}

// ---------------- Flash attention on HMMA (fp32 softmax) ----------------
// One block per (b,h), 8 warps, 19 q-tiles. K and V row-major [320][72h];
// V B-fragments via ldmatrix.trans. Fill via cp.async (full-MLP prologue).
#define KPAD 320
#define KSTR 72
#define ATT_SMEM_HALVES (2*KPAD*KSTR)
#define ATT_SMEM_BYTES  (ATT_SMEM_HALVES * 2)    // 92160

__global__ void __launch_bounds__(256, 2) attn_mma(
    const __half* __restrict__ Qb, const __half* __restrict__ Kb,
    const __half* __restrict__ Vb, __half* __restrict__ oh)
{
    extern __shared__ __half smh[];
    __half* Ks = smh;
    __half* Vs = smh + KPAD * KSTR;

    const int bh = blockIdx.x;
    const int b = bh / NHEAD, h = bh % NHEAD;
    const int tid = threadIdx.x, warp = tid >> 5, lane = tid & 31;
    const size_t ib = (size_t)bh * NTOK * 64;

    // async fill of K and V rows 0..290 (16B chunks; row stride 144B = 16B-aligned)
    const uint32_t ksm = smem_u32(Ks), vsm = smem_u32(Vs);
    for (int idx = tid; idx < NTOK * 8; idx += 256) {
        int t = idx >> 3, s = idx & 7;
        asm volatile("cp.async.cg.shared.global [%0], [%1], 16;"
            :: "r"(ksm + (t * KSTR + s * 8) * 2), "l"(Kb + ib + (size_t)t * 64 + s * 8) : "memory");
        asm volatile("cp.async.cg.shared.global [%0], [%1], 16;"
            :: "r"(vsm + (t * KSTR + s * 8) * 2), "l"(Vb + ib + (size_t)t * 64 + s * 8) : "memory");
    }
    // zero V pad rows 291..319 (NaN*0 hazard in P@V) — plain stores, overlap async
    for (int idx = tid; idx < (KPAD - NTOK) * 8; idx += 256) {
        int t = NTOK + (idx >> 3), s = idx & 7;
        ((int4*)(Vs + t * KSTR))[s] = make_int4(0, 0, 0, 0);
    }
    asm volatile("cp.async.commit_group;" ::: "memory");
    asm volatile("cp.async.wait_group 0;" ::: "memory");
    __syncthreads();

    const uint32_t ks0 = ksm, vs0 = vsm;

    for (int tile = warp; tile < 19; tile += 8) {
        // ---- Q fragments straight from gmem (canonical m16n8k16 A layout) ----
        uint32_t qf[4][4];
        {
            int r0g = tile * 16 + (lane >> 2);
            int r1g = r0g + 8;
            if (r0g >= NTOK) r0g = NTOK - 1;
            if (r1g >= NTOK) r1g = NTOK - 1;
            const __half* Q0 = Qb + ib + (size_t)r0g * 64;
            const __half* Q1 = Qb + ib + (size_t)r1g * 64;
            int c0 = (lane & 3) * 2;
#pragma unroll
            for (int ks = 0; ks < 4; ks++) {
                qf[ks][0] = *(const uint32_t*)(Q0 + ks * 16 + c0);
                qf[ks][1] = *(const uint32_t*)(Q1 + ks * 16 + c0);
                qf[ks][2] = *(const uint32_t*)(Q0 + ks * 16 + c0 + 8);
                qf[ks][3] = *(const uint32_t*)(Q1 + ks * 16 + c0 + 8);
            }
        }
        float O[8][4];
#pragma unroll
        for (int j = 0; j < 8; j++)
#pragma unroll
            for (int q = 0; q < 4; q++) O[j][q] = 0.f;
        float mr0 = -1e30f, mr1 = -1e30f, lr0 = 0.f, lr1 = 0.f;

        for (int ch = 0; ch < 5; ch++) {
            float S[8][4];
#pragma unroll
            for (int j = 0; j < 8; j++)
#pragma unroll
                for (int q = 0; q < 4; q++) S[j][q] = 0.f;

#pragma unroll
            for (int ks = 0; ks < 4; ks++) {
#pragma unroll
                for (int kg = 0; kg < 4; kg++) {
                    int trow = ch * 64 + kg * 16 + ((lane >> 4) & 1) * 8 + (lane & 7);
                    int tcol = ks * 16 + ((lane >> 3) & 1) * 8;
                    uint32_t ad = ks0 + (trow * KSTR + tcol) * 2;
                    uint32_t bfr[4];
                    LDMX4(bfr[0], bfr[1], bfr[2], bfr[3], ad);
                    mma16816(S[kg * 2],     qf[ks], bfr);
                    mma16816(S[kg * 2 + 1], qf[ks], bfr + 2);
                }
            }

            float cm0 = -1e30f, cm1 = -1e30f;
#pragma unroll
            for (int j = 0; j < 8; j++) {
                int k0c = ch * 64 + j * 8 + (lane & 3) * 2;
                if (k0c >= NTOK)     { S[j][0] = -1e30f; S[j][2] = -1e30f; }
                if (k0c + 1 >= NTOK) { S[j][1] = -1e30f; S[j][3] = -1e30f; }
                cm0 = fmaxf(cm0, fmaxf(S[j][0], S[j][1]));
                cm1 = fmaxf(cm1, fmaxf(S[j][2], S[j][3]));
            }
            cm0 = fmaxf(cm0, __shfl_xor_sync(~0u, cm0, 1));
            cm0 = fmaxf(cm0, __shfl_xor_sync(~0u, cm0, 2));
            cm1 = fmaxf(cm1, __shfl_xor_sync(~0u, cm1, 1));
            cm1 = fmaxf(cm1, __shfl_xor_sync(~0u, cm1, 2));

            float mn0 = fmaxf(mr0, cm0), mn1 = fmaxf(mr1, cm1);
            float sc0 = __expf(mr0 - mn0), sc1 = __expf(mr1 - mn1);

            float cs0 = 0.f, cs1 = 0.f;
            uint32_t pf[4][4];
#pragma unroll
            for (int j = 0; j < 8; j++) {
                float e0 = __expf(S[j][0] - mn0), e1 = __expf(S[j][1] - mn0);
                float e2 = __expf(S[j][2] - mn1), e3 = __expf(S[j][3] - mn1);
                cs0 += e0 + e1; cs1 += e2 + e3;
                __half2 p01 = __floats2half2_rn(e0, e1);
                __half2 p23 = __floats2half2_rn(e2, e3);
                int jg = j >> 1, sl = (j & 1) * 2;
                pf[jg][sl]     = reinterpret_cast<uint32_t&>(p01);
                pf[jg][sl + 1] = reinterpret_cast<uint32_t&>(p23);
            }
            cs0 += __shfl_xor_sync(~0u, cs0, 1); cs0 += __shfl_xor_sync(~0u, cs0, 2);
            cs1 += __shfl_xor_sync(~0u, cs1, 1); cs1 += __shfl_xor_sync(~0u, cs1, 2);
            lr0 = lr0 * sc0 + cs0; lr1 = lr1 * sc1 + cs1;
            mr0 = mn0; mr1 = mn1;
#pragma unroll
            for (int j = 0; j < 8; j++) {
                O[j][0] *= sc0; O[j][1] *= sc0; O[j][2] *= sc1; O[j][3] *= sc1;
            }

            // ---- O += P @ V : V row-major, B-fragments via ldmatrix.trans ----
#pragma unroll
            for (int jg = 0; jg < 4; jg++) {
#pragma unroll
                for (int dg = 0; dg < 4; dg++) {
                    int trow = ch * 64 + jg * 16 + ((lane >> 3) & 1) * 8 + (lane & 7);
                    int tcol = dg * 16 + ((lane >> 4) & 1) * 8;
                    uint32_t ad = vs0 + (trow * KSTR + tcol) * 2;
                    uint32_t bfr[4];
                    LDMX4T(bfr[0], bfr[1], bfr[2], bfr[3], ad);
                    mma16816(O[dg * 2],     pf[jg], bfr);
                    mma16816(O[dg * 2 + 1], pf[jg], bfr + 2);
                }
            }
        }

        float inv0 = 1.0f / lr0, inv1 = 1.0f / lr1;
        int r0 = tile * 16 + (lane >> 2), r1 = r0 + 8;
#pragma unroll
        for (int j = 0; j < 8; j++) {
            int d = j * 8 + (lane & 3) * 2;
            if (r0 < NTOK) {
                __half2 hv = (r0 == NTOK - 1)
                    ? *(const __half2*)(Vb + ib + (size_t)(NTOK - 1) * 64 + d)
                    : __floats2half2_rn(O[j][0] * inv0, O[j][1] * inv0);
                *(__half2*)(oh + ((size_t)b * NTOK + r0) * D_EMB + h * 64 + d) = hv;
            }
            if (r1 < NTOK) {
                __half2 hv = (r1 == NTOK - 1)
                    ? *(const __half2*)(Vb + ib + (size_t)(NTOK - 1) * 64 + d)
                    : __floats2half2_rn(O[j][2] * inv1, O[j][3] * inv1);
                *(__half2*)(oh + ((size_t)b * NTOK + r1) * D_EMB + h * 64 + d) = hv;
            }
        }
    }
}

// ---------------- tokenizers ----------------
__global__ void st_kernel(const float* __restrict__ as, const float* __restrict__ w1,
                          const float* __restrict__ b1, const float* __restrict__ w2,
                          const float* __restrict__ b2, float* __restrict__ st)
{
    __shared__ float h1[32];
    int bt = blockIdx.x;
    int tid = threadIdx.x;
    float s0 = as[bt * 2], s1 = as[bt * 2 + 1];
    if (tid < 32) {
        float v = b1[tid] + s0 * w1[tid] + s1 * w1[32 + tid];
        h1[tid] = v > 0.f ? v : 0.f;
    }
    __syncthreads();
    float acc = b2[tid];
#pragma unroll
    for (int k = 0; k < 32; k++) acc = fmaf(h1[k], w2[k * 384 + tid], acc);
    st[(size_t)bt * 384 + tid] = acc;
}

__global__ void im2col_kernel(const float* __restrict__ img, __half* __restrict__ ph)
{
    int idx = blockIdx.x * 256 + threadIdx.x;
    int f = idx % 192;
    int rem = idx / 192;
    int pidx = rem % 144;
    int bt = rem / 144;
    int pr = f / 24, pc = (f % 24) / 3, c = f % 3;
    int hp = pidx / 12, wp = pidx % 12;
    ph[idx] = __float2half_rn(img[(((size_t)bt * 3 + c) * 96 + hp * 8 + pr) * 96 + wp * 8 + pc]);
}

// assemble residual stream + xh + stat partials (block per row, 128 thr)
__global__ void assemble_ln(const float* __restrict__ imgtok, const float* __restrict__ st,
                            const float* __restrict__ readout, const float* __restrict__ pos,
                            const float* __restrict__ img_temb, const float* __restrict__ st_temb,
                            float* __restrict__ x, __half* __restrict__ xh,
                            float2* __restrict__ stats)
{
    size_t row = blockIdx.x;
    int tok = (int)(row % NTOK);
    int b = (int)(row / NTOK);
    int tid = threadIdx.x;
    float v[3];
#pragma unroll
    for (int q = 0; q < 3; q++) {
        int d = tid + q * 128;
        float vv;
        if (tok == NTOK - 1) {
            vv = readout[d];
        } else {
            int t = tok / 145, r = tok % 145;
            if (r == 0) vv = st[((size_t)(b * 2 + t)) * 384 + d] + st_temb[t * 384 + d];
            else        vv = imgtok[((size_t)(b * 2 + t) * 144 + (r - 1)) * 384 + d] + img_temb[t * 384 + d];
        }
        vv += pos[tok * 384 + d];
        v[q] = vv;
        x[row * D_EMB + d] = vv;
        xh[row * D_EMB + d] = __float2half_rn(vv);
    }
    float s = v[0] + v[1] + v[2], sq = v[0]*v[0] + v[1]*v[1] + v[2]*v[2];
#pragma unroll
    for (int o = 16; o; o >>= 1) {
        s  += __shfl_xor_sync(~0u, s,  o);
        sq += __shfl_xor_sync(~0u, sq, o);
    }
    __shared__ float ws[4], wq[4];
    int warp = tid >> 5, lane = tid & 31;
    if (!lane) { ws[warp] = s; wq[warp] = sq; }
    __syncthreads();
    if (tid == 0) {
        stats[row] = make_float2(ws[0]+ws[1]+ws[2]+ws[3], wq[0]+wq[1]+wq[2]+wq[3]);
        stats[M_TOK + row] = make_float2(0.f, 0.f);
        stats[2 * M_TOK + row] = make_float2(0.f, 0.f);
    }
}

// ---------------- launch ----------------
extern "C" void kernel_launch(void* const* d_in, const int* in_sizes, int n_in,
                              void* d_out, int out_size)
{
    const float* images      = (const float*)d_in[0];
    const float* agent_state = (const float*)d_in[1];
    const float* img_proj_w  = (const float*)d_in[2];
    const float* img_proj_b  = (const float*)d_in[3];
    const float* img_temb    = (const float*)d_in[4];
    const float* st_w1       = (const float*)d_in[5];
    const float* st_b1       = (const float*)d_in[6];
    const float* st_w2       = (const float*)d_in[7];
    const float* st_b2       = (const float*)d_in[8];
    const float* st_temb     = (const float*)d_in[9];
    const float* readout     = (const float*)d_in[10];
    const float* pos         = (const float*)d_in[11];
    const float* ln1_w       = (const float*)d_in[12];
    const float* ln1_b       = (const float*)d_in[13];
    const float* attn_w      = (const float*)d_in[14];
    const float* attn_b      = (const float*)d_in[15];
    const float* proj_w      = (const float*)d_in[16];
    const float* proj_b      = (const float*)d_in[17];
    const float* ln2_w       = (const float*)d_in[18];
    const float* ln2_b       = (const float*)d_in[19];
    const float* fc_w        = (const float*)d_in[20];
    const float* fc_b        = (const float*)d_in[21];
    const float* fc2_w       = (const float*)d_in[22];
    const float* fc2_b       = (const float*)d_in[23];
    const float* lnf_w       = (const float*)d_in[24];
    const float* lnf_b       = (const float*)d_in[25];
    float* out = (float*)d_out;

    float *x, *att, *st, *uq, *cq, *u1, *c1;
    float2 *sA, *sB;
    __half *xh, *ah, *bhp, *ph, *qb, *kb, *vb, *wq, *wp, *w1, *w2, *wi;
    cudaGetSymbolAddress((void**)&x,   g_x);
    cudaGetSymbolAddress((void**)&att, g_att);
    cudaGetSymbolAddress((void**)&st,  g_st);
    cudaGetSymbolAddress((void**)&sA,  g_sA);
    cudaGetSymbolAddress((void**)&sB,  g_sB);
    cudaGetSymbolAddress((void**)&xh,  g_xh);
    cudaGetSymbolAddress((void**)&ah,  g_ah);
    cudaGetSymbolAddress((void**)&bhp, g_bh);
    cudaGetSymbolAddress((void**)&ph,  g_ph);
    cudaGetSymbolAddress((void**)&qb,  g_q);
    cudaGetSymbolAddress((void**)&kb,  g_k);
    cudaGetSymbolAddress((void**)&vb,  g_v);
    cudaGetSymbolAddress((void**)&wq,  g_wq);
    cudaGetSymbolAddress((void**)&wp,  g_wp);
    cudaGetSymbolAddress((void**)&w1,  g_w1);
    cudaGetSymbolAddress((void**)&w2,  g_w2);
    cudaGetSymbolAddress((void**)&wi,  g_wi);
    cudaGetSymbolAddress((void**)&uq,  g_uq);
    cudaGetSymbolAddress((void**)&cq,  g_cq);
    cudaGetSymbolAddress((void**)&u1,  g_u1);
    cudaGetSymbolAddress((void**)&c1,  g_c1);

    cudaFuncSetAttribute(attn_mma, cudaFuncAttributeMaxDynamicSharedMemorySize, ATT_SMEM_BYTES);
    cudaFuncSetAttribute(gemm_mma<0>, cudaFuncAttributeMaxDynamicSharedMemorySize, GSMEM);
    cudaFuncSetAttribute(gemm_mma<3>, cudaFuncAttributeMaxDynamicSharedMemorySize, GSMEM);
    cudaFuncSetAttribute(gemm_mma<4>, cudaFuncAttributeMaxDynamicSharedMemorySize, GSMEM);
    cudaFuncSetAttribute(gemm_mma<5>, cudaFuncAttributeMaxDynamicSharedMemorySize, GSMEM);

    // ---- weight prep + LN fusion vectors ----
    wprep<<<dim3(1152/32, 384/32, 12), dim3(32, 8)>>>(attn_w, ln1_w, wq, 384, 1152);
    wprep<<<dim3(384/32,  384/32, 12), dim3(32, 8)>>>(proj_w, nullptr, wp, 384, 384);
    wprep<<<dim3(1536/32, 384/32, 12), dim3(32, 8)>>>(fc_w,  ln2_w, w1, 384, 1536);
    wprep<<<dim3(384/32, 1536/32, 12), dim3(32, 8)>>>(fc2_w, nullptr, w2, 1536, 384);
    wprep<<<dim3(384/32,  192/32, 1),  dim3(32, 8)>>>(img_proj_w, nullptr, wi, 192, 384);
    prep_uc<<<dim3(1152/128, 12), 128>>>(attn_w, ln1_w, ln1_b, attn_b, uq, cq, 1152);
    prep_uc<<<dim3(1536/128, 12), 128>>>(fc_w,  ln2_w, ln2_b, fc_b,  u1, c1, 1536);

    // ---- tokenizers ----
    st_kernel<<<BATCH * OBS_H, 384>>>(agent_state, st_w1, st_b1, st_w2, st_b2, st);
    im2col_kernel<<<(M_PATCH * PK) / 256, 256>>>(images, ph);
    gemm_mma<0><<<dim3(3, M_PATCH / 128), 256, GSMEM>>>(
        ph, wi, img_proj_b, nullptr, att, nullptr, nullptr, nullptr, nullptr,
        nullptr, nullptr, nullptr, nullptr, 384, PK);
    assemble_ln<<<M_TOK, 128>>>(att, st, readout, pos, img_temb, st_temb, x, xh, sA);

    // ---- transformer layers ----
    for (int l = 0; l < NLAYER; l++) {
        gemm_mma<4><<<dim3(9, NTOK), 256, GSMEM>>>(
            xh, wq + (size_t)l * 1152 * 384, cq + l * 1152, nullptr,
            nullptr, nullptr, qb, kb, vb, sA, nullptr, uq + l * 1152, nullptr, 1152, 384);
        attn_mma<<<BATCH * NHEAD, 256, ATT_SMEM_BYTES>>>(qb, kb, vb, ah);
        gemm_mma<5><<<dim3(3, NTOK), 256, GSMEM>>>(
            ah, wp + (size_t)l * 384 * 384, proj_b + l * 384, x,
            x, nullptr, nullptr, nullptr, nullptr, nullptr, sB, nullptr, xh, 384, 384);
        gemm_mma<3><<<dim3(12, NTOK), 256, GSMEM>>>(
            xh, w1 + (size_t)l * 1536 * 384, c1 + l * 1536, nullptr,
            nullptr, bhp, nullptr, nullptr, nullptr, sB, nullptr, u1 + l * 1536, nullptr, 1536, 384);
        gemm_mma<5><<<dim3(3, NTOK), 256, GSMEM>>>(
            bhp, w2 + (size_t)l * 384 * 1536, fc2_b + l * 384, x,
            x, nullptr, nullptr, nullptr, nullptr, nullptr, sA, nullptr, xh, 384, 1536);
    }

    lnf_kernel<<<BATCH, 128>>>(x, lnf_w, lnf_b, out);
}